// round 11
// baseline (speedup 1.0000x reference)
#include <cuda_runtime.h>
#include <cuda_bf16.h>
#include <cstdint>

#define Bn   16
#define Nn   16384
#define Sn   4096
#define Kn   16
#define FC   68      // fused channels: 64 points + 3 xyz + 1 pad
#define CMID 16
#define DOUT 128
#define AGGD 1072    // 67*16
#define KPAD 1088    // 34 * 32

// Scratch (no allocations allowed -> __device__ globals; zero-initialized)
__device__ float g_fused[(size_t)Bn * Nn * FC];              // ~71 MB
__device__ __nv_bfloat16 g_Ahi[(size_t)Bn * Sn * KPAD];      // agg hi split
__device__ __nv_bfloat16 g_Alo[(size_t)Bn * Sn * KPAD];      // agg lo split
__device__ __nv_bfloat16 g_Bhi[DOUT * KPAD];                 // wl^T hi split
__device__ __nv_bfloat16 g_Blo[DOUT * KPAD];                 // wl^T lo split

__device__ __forceinline__ uint32_t smem_u32(const void* p) {
    uint32_t a;
    asm("{ .reg .u64 t; cvta.to.shared.u64 t, %1; cvt.u32.u64 %0, t; }" : "=r"(a) : "l"(p));
    return a;
}

#define LDMX4(r0, r1, r2, r3, addr)                                            \
    asm volatile("ldmatrix.sync.aligned.m8n8.x4.shared.b16 {%0,%1,%2,%3}, [%4];" \
                 : "=r"(r0), "=r"(r1), "=r"(r2), "=r"(r3) : "r"(addr))

#define MMA16816(acc, a, b0, b1)                                               \
    asm volatile("mma.sync.aligned.m16n8k16.row.col.f32.bf16.bf16.f32 "        \
                 "{%0,%1,%2,%3},{%4,%5,%6,%7},{%8,%9},{%0,%1,%2,%3};"          \
                 : "+f"((acc)[0]), "+f"((acc)[1]), "+f"((acc)[2]), "+f"((acc)[3]) \
                 : "r"((a)[0]), "r"((a)[1]), "r"((a)[2]), "r"((a)[3]),         \
                   "r"(b0), "r"(b1))

#define CP16(dst, src)                                                         \
    asm volatile("cp.async.cg.shared.global [%0], [%1], 16;" :: "r"(dst), "l"(src))
#define CP_COMMIT() asm volatile("cp.async.commit_group;" ::: "memory")
#define CP_WAIT(n)  asm volatile("cp.async.wait_group %0;" :: "n"(n) : "memory")

#define FMA_F32X2(d, a, b, c)                                                  \
    asm("fma.rn.f32x2 %0, %1, %2, %3;"                                         \
        : "=l"(d) : "l"(a), "l"(b), "l"(c))

// ===========================================================================
// Kernel 0: point-major fused feature array (vectorized, batch-chunked)
// ===========================================================================
__global__ void k_fuse(const float* __restrict__ xyz, const float* __restrict__ points,
                       int by0)
{
    __shared__ float t[32][69];
    int b = by0 + blockIdx.y, n0 = blockIdx.x * 32;
    for (int i = threadIdx.x; i < 544; i += 256) {
        int c = i >> 3, nq = i & 7;
        float4 v = make_float4(0.f, 0.f, 0.f, 0.f);
        if (c < 64)
            v = *(const float4*)&points[((size_t)b * 64 + c) * Nn + n0 + nq * 4];
        else if (c < 67)
            v = *(const float4*)&xyz[((size_t)b * 3 + (c - 64)) * Nn + n0 + nq * 4];
        t[nq * 4 + 0][c] = v.x;
        t[nq * 4 + 1][c] = v.y;
        t[nq * 4 + 2][c] = v.z;
        t[nq * 4 + 3][c] = v.w;
    }
    __syncthreads();
    float* dst = g_fused + ((size_t)b * Nn + n0) * FC;
    for (int i = threadIdx.x; i < 544; i += 256) {
        int r = i / 17, q = i - r * 17;
        float4 v = make_float4(t[r][q * 4], t[r][q * 4 + 1],
                               t[r][q * 4 + 2], t[r][q * 4 + 3]);
        *(float4*)&dst[r * FC + q * 4] = v;
    }
}

// ===========================================================================
// LayerNorm (+ leaky 0.2) helper
// ===========================================================================
template <int NCH>
__device__ __forceinline__ void ln_leaky(float* h, const float* gmm, const float* bt)
{
    const float inv = 1.f / (float)NCH;
    float m = 0.f;
#pragma unroll
    for (int j = 0; j < NCH; j++) m += h[j];
    m *= inv;
    float v = 0.f;
#pragma unroll
    for (int j = 0; j < NCH; j++) { float d = h[j] - m; v += d * d; }
    v *= inv;
    float r = rsqrtf(v + 1e-5f);
#pragma unroll
    for (int j = 0; j < NCH; j++) {
        float y = (h[j] - m) * r * gmm[j] + bt[j];
        h[j] = y > 0.f ? y : 0.2f * y;
    }
}

// ===========================================================================
// Kernel 1: 8 points per CTA (128 threads), batch-chunked (b0 offset).
// ===========================================================================
#define PPB 8        // points per block
__global__ __launch_bounds__(128)
void k_agg(const int* __restrict__ nn_idx, const float* __restrict__ new_xyz,
           const float* __restrict__ w0, const float* __restrict__ b0,
           const float* __restrict__ gm0, const float* __restrict__ be0,
           const float* __restrict__ w1, const float* __restrict__ b1,
           const float* __restrict__ gm1, const float* __restrict__ be1,
           const float* __restrict__ w2, const float* __restrict__ b2,
           const float* __restrict__ gm2, const float* __restrict__ be2,
           int bb0)
{
    __shared__ float g[PPB][17][FC];
    __shared__ float wk[PPB][Kn][17];
    __shared__ int   idxs[PPB * Kn];
    __shared__ float nx[PPB][3];
    __shared__ float wp[312];

    int s0 = blockIdx.x * PPB, b = bb0 + blockIdx.y;
    int tid = threadIdx.x;
    int pp = tid >> 4, kk = tid & 15;

    idxs[tid] = nn_idx[((size_t)b * Sn + s0) * Kn + tid];
    if (tid < 24) {
        int d = tid >> 3, q = tid & 7;
        nx[q][d] = new_xyz[(b * 3 + d) * Sn + s0 + q];
    }

    if (tid < 24) wp[tid] = w0[tid];
    if (tid < 8) {
        wp[24 + tid] = b0[tid];  wp[32 + tid] = gm0[tid]; wp[40 + tid] = be0[tid];
        wp[112 + tid] = b1[tid]; wp[120 + tid] = gm1[tid]; wp[128 + tid] = be1[tid];
    }
    if (tid < 64) wp[48 + tid] = w1[tid];
    wp[136 + tid] = w2[tid];
    if (tid < 16) {
        wp[264 + tid] = b2[tid]; wp[280 + tid] = gm2[tid]; wp[296 + tid] = be2[tid];
    }
    __syncthreads();

    // Gather: 8 points x 16 neighbors x 17 float4
#pragma unroll
    for (int it = 0; it < 17; it++) {
        int i = tid + it * 128;
        int pg = i / 272;
        int rem = i - pg * 272;
        int kg = rem / 17;
        int cg = rem - kg * 17;
        const float4* src = (const float4*)(g_fused + ((size_t)b * Nn + idxs[pg * 16 + kg]) * FC);
        ((float4*)(&g[pg][kg][0]))[cg] = src[cg];
    }
    __syncthreads();

    // MLP: all 128 threads, one (point, neighbor) each
    {
        float x0 = g[pp][kk][64] - nx[pp][0];
        float x1 = g[pp][kk][65] - nx[pp][1];
        float x2 = g[pp][kk][66] - nx[pp][2];
        g[pp][kk][64] = x0; g[pp][kk][65] = x1; g[pp][kk][66] = x2;

        float h[8];
#pragma unroll
        for (int j = 0; j < 8; j++)
            h[j] = x0 * wp[j] + x1 * wp[8 + j] + x2 * wp[16 + j] + wp[24 + j];
        ln_leaky<8>(h, wp + 32, wp + 40);

        float h2[8];
#pragma unroll
        for (int j = 0; j < 8; j++) {
            float a = wp[112 + j];
#pragma unroll
            for (int r = 0; r < 8; r++) a += h[r] * wp[48 + r * 8 + j];
            h2[j] = a;
        }
        ln_leaky<8>(h2, wp + 120, wp + 128);

        float h3[16];
#pragma unroll
        for (int j = 0; j < 16; j++) {
            float a = wp[264 + j];
#pragma unroll
            for (int r = 0; r < 8; r++) a += h2[r] * wp[136 + r * 16 + j];
            h3[j] = a;
        }
        ln_leaky<16>(h3, wp + 280, wp + 296);
#pragma unroll
        for (int j = 0; j < 16; j++) wk[pp][kk][j] = h3[j];
    }
    __syncthreads();

    // Aggregation: fixed m-pair per thread, fma.rn.f32x2, 4 acc chains.
    {
        int t = kk;
        int p = t & 7;
        int cp0 = t >> 3;                 // 0 or 1

        unsigned long long ws0[Kn], ws1[Kn];
#pragma unroll
        for (int k = 0; k < Kn; k++) {
            float a0 = wk[pp][k][2 * p], a1 = wk[pp][k][2 * p + 1];
            asm("mov.b64 %0, {%1, %1};" : "=l"(ws0[k]) : "f"(a0));
            asm("mov.b64 %0, {%1, %1};" : "=l"(ws1[k]) : "f"(a1));
        }

        uint32_t* hrow = (uint32_t*)(g_Ahi + ((size_t)b * Sn + s0 + pp) * KPAD);
        uint32_t* lrow = (uint32_t*)(g_Alo + ((size_t)b * Sn + s0 + pp) * KPAD);

        auto emit = [&](int c, unsigned long long accA, unsigned long long accB) {
            float v00, v10, v01, v11;
            asm("mov.b64 {%0, %1}, %2;" : "=f"(v00), "=f"(v10) : "l"(accA));
            asm("mov.b64 {%0, %1}, %2;" : "=f"(v01), "=f"(v11) : "l"(accB));
            __nv_bfloat16 h00 = __float2bfloat16(v00);
            __nv_bfloat16 h01 = __float2bfloat16(v01);
            __nv_bfloat16 h10 = __float2bfloat16(v10);
            __nv_bfloat16 h11 = __float2bfloat16(v11);
            __nv_bfloat16 l00 = __float2bfloat16(v00 - __bfloat162float(h00));
            __nv_bfloat16 l01 = __float2bfloat16(v01 - __bfloat162float(h01));
            __nv_bfloat16 l10 = __float2bfloat16(v10 - __bfloat162float(h10));
            __nv_bfloat16 l11 = __float2bfloat16(v11 - __bfloat162float(h11));
            int ip0 = c * 8 + p, ip1 = (c + 1) * 8 + p;
            hrow[ip0] = (uint32_t)*(unsigned short*)&h00 | ((uint32_t)*(unsigned short*)&h01 << 16);
            hrow[ip1] = (uint32_t)*(unsigned short*)&h10 | ((uint32_t)*(unsigned short*)&h11 << 16);
            lrow[ip0] = (uint32_t)*(unsigned short*)&l00 | ((uint32_t)*(unsigned short*)&l01 << 16);
            lrow[ip1] = (uint32_t)*(unsigned short*)&l10 | ((uint32_t)*(unsigned short*)&l11 << 16);
        };

#pragma unroll 1
        for (int ii = 0; ii < 8; ii++) {
            int c0 = (cp0 + 2 * (2 * ii)) * 2;
            int c1 = (cp0 + 2 * (2 * ii + 1)) * 2;
            unsigned long long accA0 = 0ull, accB0 = 0ull;
            unsigned long long accA1 = 0ull, accB1 = 0ull;
#pragma unroll
            for (int k = 0; k < Kn; k++) {
                unsigned long long f0 = *(const unsigned long long*)&g[pp][k][c0];
                unsigned long long f1 = *(const unsigned long long*)&g[pp][k][c1];
                FMA_F32X2(accA0, f0, ws0[k], accA0);
                FMA_F32X2(accB0, f0, ws1[k], accB0);
                FMA_F32X2(accA1, f1, ws0[k], accA1);
                FMA_F32X2(accB1, f1, ws1[k], accB1);
            }
            emit(c0, accA0, accB0);
            emit(c1, accA1, accB1);
        }
        {   // tail: i = 16
            int c = (cp0 + 32) * 2;
            unsigned long long accA = 0ull, accB = 0ull;
#pragma unroll
            for (int k = 0; k < Kn; k++) {
                unsigned long long fv2 = *(const unsigned long long*)&g[pp][k][c];
                FMA_F32X2(accA, fv2, ws0[k], accA);
                FMA_F32X2(accB, fv2, ws1[k], accB);
            }
            emit(c, accA, accB);
        }
    }
}

// ===========================================================================
// Kernel 1.5: transpose wl [1072][128] -> [128][1088], split bf16 hi/lo
// ===========================================================================
__global__ void k_prepB(const float* __restrict__ wl)
{
    int idx = blockIdx.x * 256 + threadIdx.x;
    if (idx >= DOUT * KPAD) return;
    int n = idx / KPAD, k = idx - n * KPAD;
    float v = (k < AGGD) ? wl[k * DOUT + n] : 0.f;
    __nv_bfloat16 h = __float2bfloat16(v);
    __nv_bfloat16 l = __float2bfloat16(v - __bfloat162float(h));
    g_Bhi[idx] = h;
    g_Blo[idx] = l;
}

// ===========================================================================
// Kernel 2: pipelined mma.sync bf16x3 GEMM (block-chunked via blk0)
// ===========================================================================
#define PITCHB   48
#define A_SUB    6144
#define B_SUB    6144
#define B_BASE   24576
#define STAGEB   49152
#define GEMM_SMEM (2 * STAGEB)
#define TPITCH   129

__global__ __launch_bounds__(256, 2)
void k_gemm_mma(const float* __restrict__ bl, const float* __restrict__ gl,
                const float* __restrict__ bel, float* __restrict__ out, int blk0)
{
    extern __shared__ char dsm[];
    __shared__ float spb[DOUT], spg[DOUT], spe[DOUT];

    int tid = threadIdx.x;
    int wid = tid >> 5, lane = tid & 31;
    int wm = wid & 3, wn = wid >> 2;
    int m0 = (blk0 + blockIdx.x) * 128;

    if (tid < DOUT) { spb[tid] = bl[tid]; spg[tid] = gl[tid]; spe[tid] = bel[tid]; }

    uint32_t sb = smem_u32(dsm);
    uint32_t aOff = (uint32_t)((lane & 15) * PITCHB + (lane >> 4) * 16);
    uint32_t bOff = (uint32_t)(((lane >> 4) * 8 + (lane & 7)) * PITCHB + ((lane >> 3) & 1) * 16);

    float acc[2][8][4];
#pragma unroll
    for (int f = 0; f < 2; f++)
#pragma unroll
        for (int q = 0; q < 8; q++)
#pragma unroll
            for (int r = 0; r < 4; r++) acc[f][q][r] = 0.f;

    auto stage_copy = [&](int st, int c) {
        uint32_t stu = sb + st * STAGEB;
#pragma unroll
        for (int t = tid; t < 1024; t += 256) {
            int p = t >> 9, rem = t & 511, j = rem >> 8, r2 = rem & 255;
            int r = r2 >> 1, h = r2 & 1;
            const __nv_bfloat16* gA = p ? g_Alo : g_Ahi;
            const __nv_bfloat16* src = gA + (size_t)(m0 + r) * KPAD + c * 32 + j * 16 + h * 8;
            CP16(stu + (p * 2 + j) * A_SUB + r * PITCHB + h * 16, (const void*)src);
        }
#pragma unroll
        for (int t = tid; t < 1024; t += 256) {
            int p = t >> 9, rem = t & 511, j = rem >> 8, r2 = rem & 255;
            int n = r2 >> 1, h = r2 & 1;
            const __nv_bfloat16* gB = p ? g_Blo : g_Bhi;
            const __nv_bfloat16* src = gB + (size_t)n * KPAD + c * 32 + j * 16 + h * 8;
            CP16(stu + B_BASE + (p * 2 + j) * B_SUB + n * PITCHB + h * 16, (const void*)src);
        }
    };

    stage_copy(0, 0);
    CP_COMMIT();

    for (int c = 0; c < 34; c++) {
        CP_WAIT(0);
        __syncthreads();
        if (c + 1 < 34) { stage_copy((c + 1) & 1, c + 1); CP_COMMIT(); }

        uint32_t stu = sb + (c & 1) * STAGEB;
#pragma unroll
        for (int j = 0; j < 2; j++) {
            uint32_t ahi[2][4], alo[2][4], bfr[4][4];
#pragma unroll
            for (int f = 0; f < 2; f++) {
                uint32_t ra = (uint32_t)((wm * 32 + f * 16) * PITCHB) + aOff;
                LDMX4(ahi[f][0], ahi[f][1], ahi[f][2], ahi[f][3], stu + j * A_SUB + ra);
                LDMX4(alo[f][0], alo[f][1], alo[f][2], alo[f][3], stu + (2 + j) * A_SUB + ra);
            }
#pragma unroll
            for (int g = 0; g < 4; g++) {
                uint32_t rb = (uint32_t)((wn * 64 + g * 16) * PITCHB) + bOff;
                LDMX4(bfr[g][0], bfr[g][1], bfr[g][2], bfr[g][3], stu + B_BASE + j * B_SUB + rb);
            }
            // HH
#pragma unroll
            for (int g = 0; g < 4; g++)
#pragma unroll
                for (int f = 0; f < 2; f++) {
                    MMA16816(acc[f][2 * g],     ahi[f], bfr[g][0], bfr[g][1]);
                    MMA16816(acc[f][2 * g + 1], ahi[f], bfr[g][2], bfr[g][3]);
                }
            // LH
#pragma unroll
            for (int g = 0; g < 4; g++)
#pragma unroll
                for (int f = 0; f < 2; f++) {
                    MMA16816(acc[f][2 * g],     alo[f], bfr[g][0], bfr[g][1]);
                    MMA16816(acc[f][2 * g + 1], alo[f], bfr[g][2], bfr[g][3]);
                }
            // reload B-lo into same regs
#pragma unroll
            for (int g = 0; g < 4; g++) {
                uint32_t rb = (uint32_t)((wn * 64 + g * 16) * PITCHB) + bOff;
                LDMX4(bfr[g][0], bfr[g][1], bfr[g][2], bfr[g][3], stu + B_BASE + (2 + j) * B_SUB + rb);
            }
            // HL
#pragma unroll
            for (int g = 0; g < 4; g++)
#pragma unroll
                for (int f = 0; f < 2; f++) {
                    MMA16816(acc[f][2 * g],     ahi[f], bfr[g][0], bfr[g][1]);
                    MMA16816(acc[f][2 * g + 1], ahi[f], bfr[g][2], bfr[g][3]);
                }
        }
    }
    __syncthreads();

    // ---- epilogue: acc (+bias) -> T[128][129] ----
    float* T = (float*)dsm;
#pragma unroll
    for (int f = 0; f < 2; f++) {
        int r0 = wm * 32 + f * 16 + (lane >> 2);
#pragma unroll
        for (int q = 0; q < 8; q++) {
            int d = wn * 64 + q * 8 + (lane & 3) * 2;
            T[r0 * TPITCH + d]           = acc[f][q][0] + spb[d];
            T[r0 * TPITCH + d + 1]       = acc[f][q][1] + spb[d + 1];
            T[(r0 + 8) * TPITCH + d]     = acc[f][q][2] + spb[d];
            T[(r0 + 8) * TPITCH + d + 1] = acc[f][q][3] + spb[d + 1];
        }
    }
    __syncthreads();

    // ---- LayerNorm: 2 lanes per row (64 cols each) ----
    {
        int r = tid >> 1, q = tid & 1;
        float v[64];
        float s1 = 0.f, s2 = 0.f;
#pragma unroll
        for (int i = 0; i < 64; i++) {
            v[i] = T[r * TPITCH + q * 64 + i];
            s1 += v[i]; s2 += v[i] * v[i];
        }
        s1 += __shfl_xor_sync(0xffffffffu, s1, 1);
        s2 += __shfl_xor_sync(0xffffffffu, s2, 1);
        float mean = s1 * (1.f / 128.f);
        float var  = s2 * (1.f / 128.f) - mean * mean;
        float rs   = rsqrtf(var + 1e-5f);
#pragma unroll
        for (int i = 0; i < 64; i++) {
            int d = q * 64 + i;
            float y = (v[i] - mean) * rs * spg[d] + spe[d];
            T[r * TPITCH + d] = y > 0.f ? y : 0.2f * y;
        }
    }
    __syncthreads();

    // ---- coalesced transposed store ----
    int b = m0 >> 12, s0 = m0 & 4095;
    float* ob = out + (size_t)b * DOUT * Sn + s0;
    for (int i = tid; i < 128 * DOUT; i += 256) {
        int d = i >> 7, r = i & 127;
        ob[(size_t)d * Sn + r] = T[r * TPITCH + d];
    }
}

// ===========================================================================
extern "C" void kernel_launch(void* const* d_in, const int* in_sizes, int n_in,
                              void* d_out, int out_size)
{
    const float* xyz     = (const float*)d_in[0];
    const float* points  = (const float*)d_in[1];
    const float* new_xyz = (const float*)d_in[2];
    const int*   nn_idx  = (const int*)  d_in[3];
    const float* w0  = (const float*)d_in[4];
    const float* b0  = (const float*)d_in[5];
    const float* gm0 = (const float*)d_in[6];
    const float* be0 = (const float*)d_in[7];
    const float* w1  = (const float*)d_in[8];
    const float* b1  = (const float*)d_in[9];
    const float* gm1 = (const float*)d_in[10];
    const float* be1 = (const float*)d_in[11];
    const float* w2  = (const float*)d_in[12];
    const float* b2  = (const float*)d_in[13];
    const float* gm2 = (const float*)d_in[14];
    const float* be2 = (const float*)d_in[15];
    const float* wl  = (const float*)d_in[16];
    const float* bl  = (const float*)d_in[17];
    const float* gl  = (const float*)d_in[18];
    const float* bel = (const float*)d_in[19];
    float* out = (float*)d_out;

    static int inited = 0;
    static cudaStream_t sA = 0, sB = 0;
    static cudaEvent_t evF0, evF1, evA0, evA1, evB;
    if (!inited) {
        cudaFuncSetAttribute(k_gemm_mma, cudaFuncAttributeMaxDynamicSharedMemorySize,
                             GEMM_SMEM);
        cudaStreamCreateWithFlags(&sA, cudaStreamNonBlocking);
        cudaStreamCreateWithFlags(&sB, cudaStreamNonBlocking);
        cudaEventCreateWithFlags(&evF0, cudaEventDisableTiming);
        cudaEventCreateWithFlags(&evF1, cudaEventDisableTiming);
        cudaEventCreateWithFlags(&evA0, cudaEventDisableTiming);
        cudaEventCreateWithFlags(&evA1, cudaEventDisableTiming);
        cudaEventCreateWithFlags(&evB,  cudaEventDisableTiming);
        inited = 1;
    }

    const int HB = Bn / 2;                 // 8 batches per chunk

    // legacy stream: prepB, then fuse in two batch-chunks
    k_prepB<<<(DOUT * KPAD + 255) / 256, 256>>>(wl);
    {
        dim3 gF(Nn / 32, HB);
        k_fuse<<<gF, 256>>>(xyz, points, 0);
        cudaEventRecord(evF0, 0);
        k_fuse<<<gF, 256>>>(xyz, points, HB);
        cudaEventRecord(evF1, 0);
    }

    // stream A: agg chunks
    {
        dim3 gA(Sn / PPB, HB);
        cudaStreamWaitEvent(sA, evF0, 0);
        k_agg<<<gA, 128, 0, sA>>>(nn_idx, new_xyz,
                                  w0, b0, gm0, be0,
                                  w1, b1, gm1, be1,
                                  w2, b2, gm2, be2, 0);
        cudaEventRecord(evA0, sA);
        cudaStreamWaitEvent(sA, evF1, 0);
        k_agg<<<gA, 128, 0, sA>>>(nn_idx, new_xyz,
                                  w0, b0, gm0, be0,
                                  w1, b1, gm1, be1,
                                  w2, b2, gm2, be2, HB);
        cudaEventRecord(evA1, sA);
    }

    // stream B: gemm chunks (256 blocks each = 8 batches)
    {
        const int HBLK = (Bn * Sn) / 128 / 2;   // 256
        cudaStreamWaitEvent(sB, evA0, 0);
        k_gemm_mma<<<HBLK, 256, GEMM_SMEM, sB>>>(bl, gl, bel, out, 0);
        cudaStreamWaitEvent(sB, evA1, 0);
        k_gemm_mma<<<HBLK, 256, GEMM_SMEM, sB>>>(bl, gl, bel, out, HBLK);
        cudaEventRecord(evB, sB);
    }

    // rejoin legacy stream
    cudaStreamWaitEvent(0, evB, 0);
}

// round 12
// speedup vs baseline: 1.0392x; 1.0392x over previous
#include <cuda_runtime.h>
#include <cuda_bf16.h>
#include <cstdint>

#define Bn   16
#define Nn   16384
#define Sn   4096
#define Kn   16
#define FC   68      // fused channels: 64 points + 3 xyz + 1 pad
#define CMID 16
#define DOUT 128
#define AGGD 1072    // 67*16
#define KPAD 1088    // 34 * 32

// Scratch (no allocations allowed -> __device__ globals; zero-initialized)
__device__ float g_fused[(size_t)Bn * Nn * FC];              // ~71 MB
__device__ __nv_bfloat16 g_Ahi[(size_t)Bn * Sn * KPAD];      // agg hi split
__device__ __nv_bfloat16 g_Alo[(size_t)Bn * Sn * KPAD];      // agg lo split
__device__ __nv_bfloat16 g_Bhi[DOUT * KPAD];                 // wl^T hi split
__device__ __nv_bfloat16 g_Blo[DOUT * KPAD];                 // wl^T lo split

__device__ __forceinline__ uint32_t smem_u32(const void* p) {
    uint32_t a;
    asm("{ .reg .u64 t; cvta.to.shared.u64 t, %1; cvt.u32.u64 %0, t; }" : "=r"(a) : "l"(p));
    return a;
}

#define LDMX4(r0, r1, r2, r3, addr)                                            \
    asm volatile("ldmatrix.sync.aligned.m8n8.x4.shared.b16 {%0,%1,%2,%3}, [%4];" \
                 : "=r"(r0), "=r"(r1), "=r"(r2), "=r"(r3) : "r"(addr))

#define MMA16816(acc, a, b0, b1)                                               \
    asm volatile("mma.sync.aligned.m16n8k16.row.col.f32.bf16.bf16.f32 "        \
                 "{%0,%1,%2,%3},{%4,%5,%6,%7},{%8,%9},{%0,%1,%2,%3};"          \
                 : "+f"((acc)[0]), "+f"((acc)[1]), "+f"((acc)[2]), "+f"((acc)[3]) \
                 : "r"((a)[0]), "r"((a)[1]), "r"((a)[2]), "r"((a)[3]),         \
                   "r"(b0), "r"(b1))

#define CP16(dst, src)                                                         \
    asm volatile("cp.async.cg.shared.global [%0], [%1], 16;" :: "r"(dst), "l"(src))
#define CP_COMMIT() asm volatile("cp.async.commit_group;" ::: "memory")
#define CP_WAIT(n)  asm volatile("cp.async.wait_group %0;" :: "n"(n) : "memory")

#define FMA_F32X2(d, a, b, c)                                                  \
    asm("fma.rn.f32x2 %0, %1, %2, %3;"                                         \
        : "=l"(d) : "l"(a), "l"(b), "l"(c))

// ===========================================================================
// Kernel 0: point-major fused feature array (vectorized)
// ===========================================================================
__global__ void k_fuse(const float* __restrict__ xyz, const float* __restrict__ points)
{
    __shared__ float t[32][69];
    int b = blockIdx.y, n0 = blockIdx.x * 32;
    for (int i = threadIdx.x; i < 544; i += 256) {
        int c = i >> 3, nq = i & 7;
        float4 v = make_float4(0.f, 0.f, 0.f, 0.f);
        if (c < 64)
            v = *(const float4*)&points[((size_t)b * 64 + c) * Nn + n0 + nq * 4];
        else if (c < 67)
            v = *(const float4*)&xyz[((size_t)b * 3 + (c - 64)) * Nn + n0 + nq * 4];
        t[nq * 4 + 0][c] = v.x;
        t[nq * 4 + 1][c] = v.y;
        t[nq * 4 + 2][c] = v.z;
        t[nq * 4 + 3][c] = v.w;
    }
    __syncthreads();
    float* dst = g_fused + ((size_t)b * Nn + n0) * FC;
    for (int i = threadIdx.x; i < 544; i += 256) {
        int r = i / 17, q = i - r * 17;
        float4 v = make_float4(t[r][q * 4], t[r][q * 4 + 1],
                               t[r][q * 4 + 2], t[r][q * 4 + 3]);
        *(float4*)&dst[r * FC + q * 4] = v;
    }
}

// ===========================================================================
// LayerNorm (+ leaky 0.2) helper
// ===========================================================================
template <int NCH>
__device__ __forceinline__ void ln_leaky(float* h, const float* gmm, const float* bt)
{
    const float inv = 1.f / (float)NCH;
    float m = 0.f;
#pragma unroll
    for (int j = 0; j < NCH; j++) m += h[j];
    m *= inv;
    float v = 0.f;
#pragma unroll
    for (int j = 0; j < NCH; j++) { float d = h[j] - m; v += d * d; }
    v *= inv;
    float r = rsqrtf(v + 1e-5f);
#pragma unroll
    for (int j = 0; j < NCH; j++) {
        float y = (h[j] - m) * r * gmm[j] + bt[j];
        h[j] = y > 0.f ? y : 0.2f * y;
    }
}

// ===========================================================================
// Kernel 1: 8 points per CTA (128 threads). MLP on all threads; aggregation
//   via LDS.128 feeding 4 fma.rn.f32x2 chains; trunc/PRMT hi-lo split.
// ===========================================================================
#define PPB 8        // points per block
__global__ __launch_bounds__(128)
void k_agg(const int* __restrict__ nn_idx, const float* __restrict__ new_xyz,
           const float* __restrict__ w0, const float* __restrict__ b0,
           const float* __restrict__ gm0, const float* __restrict__ be0,
           const float* __restrict__ w1, const float* __restrict__ b1,
           const float* __restrict__ gm1, const float* __restrict__ be1,
           const float* __restrict__ w2, const float* __restrict__ b2,
           const float* __restrict__ gm2, const float* __restrict__ be2)
{
    __shared__ float g[PPB][17][FC];
    __shared__ float wk[PPB][Kn][17];
    __shared__ int   idxs[PPB * Kn];
    __shared__ float nx[PPB][3];
    __shared__ float wp[312];

    int s0 = blockIdx.x * PPB, b = blockIdx.y;
    int tid = threadIdx.x;
    int pp = tid >> 4, kk = tid & 15;

    idxs[tid] = nn_idx[((size_t)b * Sn + s0) * Kn + tid];
    if (tid < 24) {
        int d = tid >> 3, q = tid & 7;
        nx[q][d] = new_xyz[(b * 3 + d) * Sn + s0 + q];
    }

    if (tid < 24) wp[tid] = w0[tid];
    if (tid < 8) {
        wp[24 + tid] = b0[tid];  wp[32 + tid] = gm0[tid]; wp[40 + tid] = be0[tid];
        wp[112 + tid] = b1[tid]; wp[120 + tid] = gm1[tid]; wp[128 + tid] = be1[tid];
    }
    if (tid < 64) wp[48 + tid] = w1[tid];
    wp[136 + tid] = w2[tid];
    if (tid < 16) {
        wp[264 + tid] = b2[tid]; wp[280 + tid] = gm2[tid]; wp[296 + tid] = be2[tid];
    }
    __syncthreads();

    // Gather: 8 points x 16 neighbors x 17 float4
#pragma unroll
    for (int it = 0; it < 17; it++) {
        int i = tid + it * 128;
        int pg = i / 272;
        int rem = i - pg * 272;
        int kg = rem / 17;
        int cg = rem - kg * 17;
        const float4* src = (const float4*)(g_fused + ((size_t)b * Nn + idxs[pg * 16 + kg]) * FC);
        ((float4*)(&g[pg][kg][0]))[cg] = src[cg];
    }
    __syncthreads();

    // MLP: all 128 threads, one (point, neighbor) each
    {
        float x0 = g[pp][kk][64] - nx[pp][0];
        float x1 = g[pp][kk][65] - nx[pp][1];
        float x2 = g[pp][kk][66] - nx[pp][2];
        g[pp][kk][64] = x0; g[pp][kk][65] = x1; g[pp][kk][66] = x2;

        float h[8];
#pragma unroll
        for (int j = 0; j < 8; j++)
            h[j] = x0 * wp[j] + x1 * wp[8 + j] + x2 * wp[16 + j] + wp[24 + j];
        ln_leaky<8>(h, wp + 32, wp + 40);

        float h2[8];
#pragma unroll
        for (int j = 0; j < 8; j++) {
            float a = wp[112 + j];
#pragma unroll
            for (int r = 0; r < 8; r++) a += h[r] * wp[48 + r * 8 + j];
            h2[j] = a;
        }
        ln_leaky<8>(h2, wp + 120, wp + 128);

        float h3[16];
#pragma unroll
        for (int j = 0; j < 16; j++) {
            float a = wp[264 + j];
#pragma unroll
            for (int r = 0; r < 8; r++) a += h2[r] * wp[136 + r * 16 + j];
            h3[j] = a;
        }
        ln_leaky<16>(h3, wp + 280, wp + 296);
#pragma unroll
        for (int j = 0; j < 16; j++) wk[pp][kk][j] = h3[j];
    }
    __syncthreads();

    // Aggregation. thread = (point pp, slot t); m-pair p = t&7 fixed,
    // splat-packed weights. Main loop: one LDS.128 per k covers c..c+3,
    // feeding 4 independent fma.rn.f32x2 chains. Coverage: c = 4*cp0 + 8*ii
    // spans 0..63; tail c = 64 + 2*cp0 covers 64..67.
    {
        int t = kk;
        int p = t & 7;
        int cp0 = t >> 3;                 // 0 or 1

        unsigned long long ws0[Kn], ws1[Kn];
#pragma unroll
        for (int k = 0; k < Kn; k++) {
            float a0 = wk[pp][k][2 * p], a1 = wk[pp][k][2 * p + 1];
            asm("mov.b64 %0, {%1, %1};" : "=l"(ws0[k]) : "f"(a0));
            asm("mov.b64 %0, {%1, %1};" : "=l"(ws1[k]) : "f"(a1));
        }

        uint32_t* hrow = (uint32_t*)(g_Ahi + ((size_t)b * Sn + s0 + pp) * KPAD);
        uint32_t* lrow = (uint32_t*)(g_Alo + ((size_t)b * Sn + s0 + pp) * KPAD);

        // emit values for c-pair (c, c+1): accA holds (m=2p) for c and c+1,
        // accB holds (m=2p+1). hi = truncated top-16 bits (PRMT-packed);
        // lo = bf16(v - trunc(v)) pair-converted by one cvt.bf16x2.
        auto emit = [&](int c, unsigned long long accA, unsigned long long accB) {
            uint32_t a0 = (uint32_t)accA, a1 = (uint32_t)(accA >> 32);
            uint32_t e0 = (uint32_t)accB, e1 = (uint32_t)(accB >> 32);
            uint32_t hi0 = __byte_perm(a0, e0, 0x7632);
            uint32_t hi1 = __byte_perm(a1, e1, 0x7632);
            float r00 = __uint_as_float(a0) - __uint_as_float(a0 & 0xFFFF0000u);
            float r01 = __uint_as_float(e0) - __uint_as_float(e0 & 0xFFFF0000u);
            float r10 = __uint_as_float(a1) - __uint_as_float(a1 & 0xFFFF0000u);
            float r11 = __uint_as_float(e1) - __uint_as_float(e1 & 0xFFFF0000u);
            uint32_t lo0, lo1;
            asm("cvt.rn.satfinite.bf16x2.f32 %0, %1, %2;" : "=r"(lo0) : "f"(r01), "f"(r00));
            asm("cvt.rn.satfinite.bf16x2.f32 %0, %1, %2;" : "=r"(lo1) : "f"(r11), "f"(r10));
            int ip0 = c * 8 + p, ip1 = (c + 1) * 8 + p;
            hrow[ip0] = hi0; hrow[ip1] = hi1;
            lrow[ip0] = lo0; lrow[ip1] = lo1;
        };

#pragma unroll 1
        for (int ii = 0; ii < 8; ii++) {
            int c = 4 * cp0 + 8 * ii;     // 16B-aligned within row
            unsigned long long accA0 = 0ull, accB0 = 0ull;
            unsigned long long accA1 = 0ull, accB1 = 0ull;
#pragma unroll
            for (int k = 0; k < Kn; k++) {
                ulonglong2 fv = *(const ulonglong2*)&g[pp][k][c];
                FMA_F32X2(accA0, fv.x, ws0[k], accA0);
                FMA_F32X2(accB0, fv.x, ws1[k], accB0);
                FMA_F32X2(accA1, fv.y, ws0[k], accA1);
                FMA_F32X2(accB1, fv.y, ws1[k], accB1);
            }
            emit(c,     accA0, accB0);
            emit(c + 2, accA1, accB1);
        }
        {   // tail: c = 64 + 2*cp0 (covers c..c+1; c=66 pair includes zero pad c=67)
            int c = 64 + 2 * cp0;
            unsigned long long accA = 0ull, accB = 0ull;
#pragma unroll
            for (int k = 0; k < Kn; k++) {
                unsigned long long fv2 = *(const unsigned long long*)&g[pp][k][c];
                FMA_F32X2(accA, fv2, ws0[k], accA);
                FMA_F32X2(accB, fv2, ws1[k], accB);
            }
            emit(c, accA, accB);
        }
    }
}

// ===========================================================================
// Kernel 1.5: transpose wl [1072][128] -> [128][1088], split bf16 hi/lo
// ===========================================================================
__global__ void k_prepB(const float* __restrict__ wl)
{
    int idx = blockIdx.x * 256 + threadIdx.x;
    if (idx >= DOUT * KPAD) return;
    int n = idx / KPAD, k = idx - n * KPAD;
    float v = (k < AGGD) ? wl[k * DOUT + n] : 0.f;
    __nv_bfloat16 h = __float2bfloat16(v);
    __nv_bfloat16 l = __float2bfloat16(v - __bfloat162float(h));
    g_Bhi[idx] = h;
    g_Blo[idx] = l;
}

// ===========================================================================
// Kernel 2: pipelined mma.sync bf16x3 GEMM (unchanged — at HMMA roofline)
// ===========================================================================
#define PITCHB   48
#define A_SUB    6144
#define B_SUB    6144
#define B_BASE   24576
#define STAGEB   49152
#define GEMM_SMEM (2 * STAGEB)
#define TPITCH   129

__global__ __launch_bounds__(256, 2)
void k_gemm_mma(const float* __restrict__ bl, const float* __restrict__ gl,
                const float* __restrict__ bel, float* __restrict__ out)
{
    extern __shared__ char dsm[];
    __shared__ float spb[DOUT], spg[DOUT], spe[DOUT];

    int tid = threadIdx.x;
    int wid = tid >> 5, lane = tid & 31;
    int wm = wid & 3, wn = wid >> 2;
    int m0 = blockIdx.x * 128;

    if (tid < DOUT) { spb[tid] = bl[tid]; spg[tid] = gl[tid]; spe[tid] = bel[tid]; }

    uint32_t sb = smem_u32(dsm);
    uint32_t aOff = (uint32_t)((lane & 15) * PITCHB + (lane >> 4) * 16);
    uint32_t bOff = (uint32_t)(((lane >> 4) * 8 + (lane & 7)) * PITCHB + ((lane >> 3) & 1) * 16);

    float acc[2][8][4];
#pragma unroll
    for (int f = 0; f < 2; f++)
#pragma unroll
        for (int q = 0; q < 8; q++)
#pragma unroll
            for (int r = 0; r < 4; r++) acc[f][q][r] = 0.f;

    auto stage_copy = [&](int st, int c) {
        uint32_t stu = sb + st * STAGEB;
#pragma unroll
        for (int t = tid; t < 1024; t += 256) {
            int p = t >> 9, rem = t & 511, j = rem >> 8, r2 = rem & 255;
            int r = r2 >> 1, h = r2 & 1;
            const __nv_bfloat16* gA = p ? g_Alo : g_Ahi;
            const __nv_bfloat16* src = gA + (size_t)(m0 + r) * KPAD + c * 32 + j * 16 + h * 8;
            CP16(stu + (p * 2 + j) * A_SUB + r * PITCHB + h * 16, (const void*)src);
        }
#pragma unroll
        for (int t = tid; t < 1024; t += 256) {
            int p = t >> 9, rem = t & 511, j = rem >> 8, r2 = rem & 255;
            int n = r2 >> 1, h = r2 & 1;
            const __nv_bfloat16* gB = p ? g_Blo : g_Bhi;
            const __nv_bfloat16* src = gB + (size_t)n * KPAD + c * 32 + j * 16 + h * 8;
            CP16(stu + B_BASE + (p * 2 + j) * B_SUB + n * PITCHB + h * 16, (const void*)src);
        }
    };

    stage_copy(0, 0);
    CP_COMMIT();

    for (int c = 0; c < 34; c++) {
        CP_WAIT(0);
        __syncthreads();
        if (c + 1 < 34) { stage_copy((c + 1) & 1, c + 1); CP_COMMIT(); }

        uint32_t stu = sb + (c & 1) * STAGEB;
#pragma unroll
        for (int j = 0; j < 2; j++) {
            uint32_t ahi[2][4], alo[2][4], bfr[4][4];
#pragma unroll
            for (int f = 0; f < 2; f++) {
                uint32_t ra = (uint32_t)((wm * 32 + f * 16) * PITCHB) + aOff;
                LDMX4(ahi[f][0], ahi[f][1], ahi[f][2], ahi[f][3], stu + j * A_SUB + ra);
                LDMX4(alo[f][0], alo[f][1], alo[f][2], alo[f][3], stu + (2 + j) * A_SUB + ra);
            }
#pragma unroll
            for (int g = 0; g < 4; g++) {
                uint32_t rb = (uint32_t)((wn * 64 + g * 16) * PITCHB) + bOff;
                LDMX4(bfr[g][0], bfr[g][1], bfr[g][2], bfr[g][3], stu + B_BASE + j * B_SUB + rb);
            }
            // HH
#pragma unroll
            for (int g = 0; g < 4; g++)
#pragma unroll
                for (int f = 0; f < 2; f++) {
                    MMA16816(acc[f][2 * g],     ahi[f], bfr[g][0], bfr[g][1]);
                    MMA16816(acc[f][2 * g + 1], ahi[f], bfr[g][2], bfr[g][3]);
                }
            // LH
#pragma unroll
            for (int g = 0; g < 4; g++)
#pragma unroll
                for (int f = 0; f < 2; f++) {
                    MMA16816(acc[f][2 * g],     alo[f], bfr[g][0], bfr[g][1]);
                    MMA16816(acc[f][2 * g + 1], alo[f], bfr[g][2], bfr[g][3]);
                }
            // reload B-lo into same regs
#pragma unroll
            for (int g = 0; g < 4; g++) {
                uint32_t rb = (uint32_t)((wn * 64 + g * 16) * PITCHB) + bOff;
                LDMX4(bfr[g][0], bfr[g][1], bfr[g][2], bfr[g][3], stu + B_BASE + (2 + j) * B_SUB + rb);
            }
            // HL
#pragma unroll
            for (int g = 0; g < 4; g++)
#pragma unroll
                for (int f = 0; f < 2; f++) {
                    MMA16816(acc[f][2 * g],     ahi[f], bfr[g][0], bfr[g][1]);
                    MMA16816(acc[f][2 * g + 1], ahi[f], bfr[g][2], bfr[g][3]);
                }
        }
    }
    __syncthreads();

    // ---- epilogue: acc (+bias) -> T[128][129] ----
    float* T = (float*)dsm;
#pragma unroll
    for (int f = 0; f < 2; f++) {
        int r0 = wm * 32 + f * 16 + (lane >> 2);
#pragma unroll
        for (int q = 0; q < 8; q++) {
            int d = wn * 64 + q * 8 + (lane & 3) * 2;
            T[r0 * TPITCH + d]           = acc[f][q][0] + spb[d];
            T[r0 * TPITCH + d + 1]       = acc[f][q][1] + spb[d + 1];
            T[(r0 + 8) * TPITCH + d]     = acc[f][q][2] + spb[d];
            T[(r0 + 8) * TPITCH + d + 1] = acc[f][q][3] + spb[d + 1];
        }
    }
    __syncthreads();

    // ---- LayerNorm: 2 lanes per row (64 cols each) ----
    {
        int r = tid >> 1, q = tid & 1;
        float v[64];
        float s1 = 0.f, s2 = 0.f;
#pragma unroll
        for (int i = 0; i < 64; i++) {
            v[i] = T[r * TPITCH + q * 64 + i];
            s1 += v[i]; s2 += v[i] * v[i];
        }
        s1 += __shfl_xor_sync(0xffffffffu, s1, 1);
        s2 += __shfl_xor_sync(0xffffffffu, s2, 1);
        float mean = s1 * (1.f / 128.f);
        float var  = s2 * (1.f / 128.f) - mean * mean;
        float rs   = rsqrtf(var + 1e-5f);
#pragma unroll
        for (int i = 0; i < 64; i++) {
            int d = q * 64 + i;
            float y = (v[i] - mean) * rs * spg[d] + spe[d];
            T[r * TPITCH + d] = y > 0.f ? y : 0.2f * y;
        }
    }
    __syncthreads();

    // ---- coalesced transposed store ----
    int b = m0 >> 12, s0 = m0 & 4095;
    float* ob = out + (size_t)b * DOUT * Sn + s0;
    for (int i = tid; i < 128 * DOUT; i += 256) {
        int d = i >> 7, r = i & 127;
        ob[(size_t)d * Sn + r] = T[r * TPITCH + d];
    }
}

// ===========================================================================
extern "C" void kernel_launch(void* const* d_in, const int* in_sizes, int n_in,
                              void* d_out, int out_size)
{
    const float* xyz     = (const float*)d_in[0];
    const float* points  = (const float*)d_in[1];
    const float* new_xyz = (const float*)d_in[2];
    const int*   nn_idx  = (const int*)  d_in[3];
    const float* w0  = (const float*)d_in[4];
    const float* b0  = (const float*)d_in[5];
    const float* gm0 = (const float*)d_in[6];
    const float* be0 = (const float*)d_in[7];
    const float* w1  = (const float*)d_in[8];
    const float* b1  = (const float*)d_in[9];
    const float* gm1 = (const float*)d_in[10];
    const float* be1 = (const float*)d_in[11];
    const float* w2  = (const float*)d_in[12];
    const float* b2  = (const float*)d_in[13];
    const float* gm2 = (const float*)d_in[14];
    const float* be2 = (const float*)d_in[15];
    const float* wl  = (const float*)d_in[16];
    const float* bl  = (const float*)d_in[17];
    const float* gl  = (const float*)d_in[18];
    const float* bel = (const float*)d_in[19];
    float* out = (float*)d_out;

    static int inited = 0;
    if (!inited) {
        cudaFuncSetAttribute(k_gemm_mma, cudaFuncAttributeMaxDynamicSharedMemorySize,
                             GEMM_SMEM);
        inited = 1;
    }

    dim3 gFuse(Nn / 32, Bn);
    k_fuse<<<gFuse, 256>>>(xyz, points);

    k_prepB<<<(DOUT * KPAD + 255) / 256, 256>>>(wl);

    dim3 gAgg(Sn / PPB, Bn);
    k_agg<<<gAgg, 128>>>(nn_idx, new_xyz,
                         w0, b0, gm0, be0,
                         w1, b1, gm1, be1,
                         w2, b2, gm2, be2);

    k_gemm_mma<<<(Bn * Sn) / 128, 256, GEMM_SMEM>>>(bl, gl, bel, out);
}

// round 13
// speedup vs baseline: 1.0721x; 1.0317x over previous
#include <cuda_runtime.h>
#include <cuda_bf16.h>
#include <cstdint>

#define Bn   16
#define Nn   16384
#define Sn   4096
#define Kn   16
#define FC   68      // fused channels: 64 points + 3 xyz + 1 pad
#define CMID 16
#define DOUT 128
#define AGGD 1072    // 67*16
#define KPAD 1088    // 34 * 32

// Scratch (no allocations allowed -> __device__ globals; zero-initialized)
__device__ float g_fused[(size_t)Bn * Nn * FC];              // ~71 MB
__device__ __nv_bfloat16 g_Ahi[(size_t)Bn * Sn * KPAD];      // agg hi split
__device__ __nv_bfloat16 g_Alo[(size_t)Bn * Sn * KPAD];      // agg lo split
__device__ __nv_bfloat16 g_Bhi[DOUT * KPAD];                 // wl^T hi split
__device__ __nv_bfloat16 g_Blo[DOUT * KPAD];                 // wl^T lo split

__device__ __forceinline__ uint32_t smem_u32(const void* p) {
    uint32_t a;
    asm("{ .reg .u64 t; cvta.to.shared.u64 t, %1; cvt.u32.u64 %0, t; }" : "=r"(a) : "l"(p));
    return a;
}

#define LDMX4(r0, r1, r2, r3, addr)                                            \
    asm volatile("ldmatrix.sync.aligned.m8n8.x4.shared.b16 {%0,%1,%2,%3}, [%4];" \
                 : "=r"(r0), "=r"(r1), "=r"(r2), "=r"(r3) : "r"(addr))

#define MMA16816(acc, a, b0, b1)                                               \
    asm volatile("mma.sync.aligned.m16n8k16.row.col.f32.bf16.bf16.f32 "        \
                 "{%0,%1,%2,%3},{%4,%5,%6,%7},{%8,%9},{%0,%1,%2,%3};"          \
                 : "+f"((acc)[0]), "+f"((acc)[1]), "+f"((acc)[2]), "+f"((acc)[3]) \
                 : "r"((a)[0]), "r"((a)[1]), "r"((a)[2]), "r"((a)[3]),         \
                   "r"(b0), "r"(b1))

#define CP16(dst, src)                                                         \
    asm volatile("cp.async.cg.shared.global [%0], [%1], 16;" :: "r"(dst), "l"(src))
#define CP_COMMIT() asm volatile("cp.async.commit_group;" ::: "memory")
#define CP_WAIT(n)  asm volatile("cp.async.wait_group %0;" :: "n"(n) : "memory")

#define FMA_F32X2(d, a, b, c)                                                  \
    asm("fma.rn.f32x2 %0, %1, %2, %3;"                                         \
        : "=l"(d) : "l"(a), "l"(b), "l"(c))

// ===========================================================================
// Kernel 0: point-major fused feature array (vectorized)
// ===========================================================================
__global__ void k_fuse(const float* __restrict__ xyz, const float* __restrict__ points)
{
    __shared__ float t[32][69];
    int b = blockIdx.y, n0 = blockIdx.x * 32;
    for (int i = threadIdx.x; i < 544; i += 256) {
        int c = i >> 3, nq = i & 7;
        float4 v = make_float4(0.f, 0.f, 0.f, 0.f);
        if (c < 64)
            v = *(const float4*)&points[((size_t)b * 64 + c) * Nn + n0 + nq * 4];
        else if (c < 67)
            v = *(const float4*)&xyz[((size_t)b * 3 + (c - 64)) * Nn + n0 + nq * 4];
        t[nq * 4 + 0][c] = v.x;
        t[nq * 4 + 1][c] = v.y;
        t[nq * 4 + 2][c] = v.z;
        t[nq * 4 + 3][c] = v.w;
    }
    __syncthreads();
    float* dst = g_fused + ((size_t)b * Nn + n0) * FC;
    for (int i = threadIdx.x; i < 544; i += 256) {
        int r = i / 17, q = i - r * 17;
        float4 v = make_float4(t[r][q * 4], t[r][q * 4 + 1],
                               t[r][q * 4 + 2], t[r][q * 4 + 3]);
        *(float4*)&dst[r * FC + q * 4] = v;
    }
}

// ===========================================================================
// LayerNorm (+ leaky 0.2) helper
// ===========================================================================
template <int NCH>
__device__ __forceinline__ void ln_leaky(float* h, const float* gmm, const float* bt)
{
    const float inv = 1.f / (float)NCH;
    float m = 0.f;
#pragma unroll
    for (int j = 0; j < NCH; j++) m += h[j];
    m *= inv;
    float v = 0.f;
#pragma unroll
    for (int j = 0; j < NCH; j++) { float d = h[j] - m; v += d * d; }
    v *= inv;
    float r = rsqrtf(v + 1e-5f);
#pragma unroll
    for (int j = 0; j < NCH; j++) {
        float y = (h[j] - m) * r * gmm[j] + bt[j];
        h[j] = y > 0.f ? y : 0.2f * y;
    }
}

// ===========================================================================
// Kernel 1: 8 points per CTA (128 threads). Flat smem (43.9 KB) so a 5th CTA
//   can fit per SM. Same math as R12 (LDS.128 + 4 fma.rn.f32x2 chains,
//   trunc/PRMT hi-lo split).
// Smem word-layout:
//   g:    pp*1092 + k*68 + c   (pp stagger: 1092 % 32 = 4; rows 16B-aligned)
//   wk:   WK_OFF + pp*256 + k*16 + j
//   wp:   WP_OFF .. +311 ; idxs: IDX_OFF (int) ; nx: NX_OFF (8x3)
// ===========================================================================
#define PPB 8
#define GW_PP  1092
#define WK_OFF 8732              // 7*1092 + 1088
#define WP_OFF (WK_OFF + 2048)   // 10780
#define IDX_OFF (WP_OFF + 312)   // 11092
#define NX_OFF (IDX_OFF + 128)   // 11220
#define S_WORDS (NX_OFF + 24)    // 11244 words = 44976 bytes

__global__ __launch_bounds__(128, 5)
void k_agg(const int* __restrict__ nn_idx, const float* __restrict__ new_xyz,
           const float* __restrict__ w0, const float* __restrict__ b0,
           const float* __restrict__ gm0, const float* __restrict__ be0,
           const float* __restrict__ w1, const float* __restrict__ b1,
           const float* __restrict__ gm1, const float* __restrict__ be1,
           const float* __restrict__ w2, const float* __restrict__ b2,
           const float* __restrict__ gm2, const float* __restrict__ be2)
{
    __shared__ float S[S_WORDS];
    float* wp = S + WP_OFF;
    int*   idxs = (int*)(S + IDX_OFF);
    float* nx = S + NX_OFF;

    int s0 = blockIdx.x * PPB, b = blockIdx.y;
    int tid = threadIdx.x;
    int pp = tid >> 4, kk = tid & 15;

    idxs[tid] = nn_idx[((size_t)b * Sn + s0) * Kn + tid];
    if (tid < 24) {
        int d = tid >> 3, q = tid & 7;
        nx[q * 3 + d] = new_xyz[(b * 3 + d) * Sn + s0 + q];
    }

    if (tid < 24) wp[tid] = w0[tid];
    if (tid < 8) {
        wp[24 + tid] = b0[tid];  wp[32 + tid] = gm0[tid]; wp[40 + tid] = be0[tid];
        wp[112 + tid] = b1[tid]; wp[120 + tid] = gm1[tid]; wp[128 + tid] = be1[tid];
    }
    if (tid < 64) wp[48 + tid] = w1[tid];
    wp[136 + tid] = w2[tid];
    if (tid < 16) {
        wp[264 + tid] = b2[tid]; wp[280 + tid] = gm2[tid]; wp[296 + tid] = be2[tid];
    }
    __syncthreads();

    // Gather: 8 points x 16 neighbors x 17 float4
#pragma unroll
    for (int it = 0; it < 17; it++) {
        int i = tid + it * 128;
        int pg = i / 272;
        int rem = i - pg * 272;
        int kg = rem / 17;
        int cg = rem - kg * 17;
        const float4* src = (const float4*)(g_fused + ((size_t)b * Nn + idxs[pg * 16 + kg]) * FC);
        ((float4*)(S + pg * GW_PP + kg * 68))[cg] = src[cg];
    }
    __syncthreads();

    // MLP: all 128 threads, one (point, neighbor) each
    {
        float* grow = S + pp * GW_PP + kk * 68;
        float x0 = grow[64] - nx[pp * 3 + 0];
        float x1 = grow[65] - nx[pp * 3 + 1];
        float x2 = grow[66] - nx[pp * 3 + 2];
        grow[64] = x0; grow[65] = x1; grow[66] = x2;

        float h[8];
#pragma unroll
        for (int j = 0; j < 8; j++)
            h[j] = x0 * wp[j] + x1 * wp[8 + j] + x2 * wp[16 + j] + wp[24 + j];
        ln_leaky<8>(h, wp + 32, wp + 40);

        float h2[8];
#pragma unroll
        for (int j = 0; j < 8; j++) {
            float a = wp[112 + j];
#pragma unroll
            for (int r = 0; r < 8; r++) a += h[r] * wp[48 + r * 8 + j];
            h2[j] = a;
        }
        ln_leaky<8>(h2, wp + 120, wp + 128);

        float h3[16];
#pragma unroll
        for (int j = 0; j < 16; j++) {
            float a = wp[264 + j];
#pragma unroll
            for (int r = 0; r < 8; r++) a += h2[r] * wp[136 + r * 16 + j];
            h3[j] = a;
        }
        ln_leaky<16>(h3, wp + 280, wp + 296);
#pragma unroll
        for (int j = 0; j < 16; j++) S[WK_OFF + pp * 256 + kk * 16 + j] = h3[j];
    }
    __syncthreads();

    // Aggregation (identical math to R12)
    {
        int t = kk;
        int p = t & 7;
        int cp0 = t >> 3;                 // 0 or 1

        unsigned long long ws0[Kn], ws1[Kn];
#pragma unroll
        for (int k = 0; k < Kn; k++) {
            float a0 = S[WK_OFF + pp * 256 + k * 16 + 2 * p];
            float a1 = S[WK_OFF + pp * 256 + k * 16 + 2 * p + 1];
            asm("mov.b64 %0, {%1, %1};" : "=l"(ws0[k]) : "f"(a0));
            asm("mov.b64 %0, {%1, %1};" : "=l"(ws1[k]) : "f"(a1));
        }

        uint32_t* hrow = (uint32_t*)(g_Ahi + ((size_t)b * Sn + s0 + pp) * KPAD);
        uint32_t* lrow = (uint32_t*)(g_Alo + ((size_t)b * Sn + s0 + pp) * KPAD);

        auto emit = [&](int c, unsigned long long accA, unsigned long long accB) {
            uint32_t a0 = (uint32_t)accA, a1 = (uint32_t)(accA >> 32);
            uint32_t e0 = (uint32_t)accB, e1 = (uint32_t)(accB >> 32);
            uint32_t hi0 = __byte_perm(a0, e0, 0x7632);
            uint32_t hi1 = __byte_perm(a1, e1, 0x7632);
            float r00 = __uint_as_float(a0) - __uint_as_float(a0 & 0xFFFF0000u);
            float r01 = __uint_as_float(e0) - __uint_as_float(e0 & 0xFFFF0000u);
            float r10 = __uint_as_float(a1) - __uint_as_float(a1 & 0xFFFF0000u);
            float r11 = __uint_as_float(e1) - __uint_as_float(e1 & 0xFFFF0000u);
            uint32_t lo0, lo1;
            asm("cvt.rn.satfinite.bf16x2.f32 %0, %1, %2;" : "=r"(lo0) : "f"(r01), "f"(r00));
            asm("cvt.rn.satfinite.bf16x2.f32 %0, %1, %2;" : "=r"(lo1) : "f"(r11), "f"(r10));
            int ip0 = c * 8 + p, ip1 = (c + 1) * 8 + p;
            hrow[ip0] = hi0; hrow[ip1] = hi1;
            lrow[ip0] = lo0; lrow[ip1] = lo1;
        };

        const float* gbase = S + pp * GW_PP;
#pragma unroll 1
        for (int ii = 0; ii < 8; ii++) {
            int c = 4 * cp0 + 8 * ii;
            unsigned long long accA0 = 0ull, accB0 = 0ull;
            unsigned long long accA1 = 0ull, accB1 = 0ull;
#pragma unroll
            for (int k = 0; k < Kn; k++) {
                ulonglong2 fv = *(const ulonglong2*)(gbase + k * 68 + c);
                FMA_F32X2(accA0, fv.x, ws0[k], accA0);
                FMA_F32X2(accB0, fv.x, ws1[k], accB0);
                FMA_F32X2(accA1, fv.y, ws0[k], accA1);
                FMA_F32X2(accB1, fv.y, ws1[k], accB1);
            }
            emit(c,     accA0, accB0);
            emit(c + 2, accA1, accB1);
        }
        {   // tail: c = 64 + 2*cp0
            int c = 64 + 2 * cp0;
            unsigned long long accA = 0ull, accB = 0ull;
#pragma unroll
            for (int k = 0; k < Kn; k++) {
                unsigned long long fv2 = *(const unsigned long long*)(gbase + k * 68 + c);
                FMA_F32X2(accA, fv2, ws0[k], accA);
                FMA_F32X2(accB, fv2, ws1[k], accB);
            }
            emit(c, accA, accB);
        }
    }
}

// ===========================================================================
// Kernel 1.5: transpose wl [1072][128] -> [128][1088], split bf16 hi/lo
// ===========================================================================
__global__ void k_prepB(const float* __restrict__ wl)
{
    int idx = blockIdx.x * 256 + threadIdx.x;
    if (idx >= DOUT * KPAD) return;
    int n = idx / KPAD, k = idx - n * KPAD;
    float v = (k < AGGD) ? wl[k * DOUT + n] : 0.f;
    __nv_bfloat16 h = __float2bfloat16(v);
    __nv_bfloat16 l = __float2bfloat16(v - __bfloat162float(h));
    g_Bhi[idx] = h;
    g_Blo[idx] = l;
}

// ===========================================================================
// Kernel 2: pipelined mma.sync bf16x3 GEMM (unchanged — at HMMA cap)
// ===========================================================================
#define PITCHB   48
#define A_SUB    6144
#define B_SUB    6144
#define B_BASE   24576
#define STAGEB   49152
#define GEMM_SMEM (2 * STAGEB)
#define TPITCH   129

__global__ __launch_bounds__(256, 2)
void k_gemm_mma(const float* __restrict__ bl, const float* __restrict__ gl,
                const float* __restrict__ bel, float* __restrict__ out)
{
    extern __shared__ char dsm[];
    __shared__ float spb[DOUT], spg[DOUT], spe[DOUT];

    int tid = threadIdx.x;
    int wid = tid >> 5, lane = tid & 31;
    int wm = wid & 3, wn = wid >> 2;
    int m0 = blockIdx.x * 128;

    if (tid < DOUT) { spb[tid] = bl[tid]; spg[tid] = gl[tid]; spe[tid] = bel[tid]; }

    uint32_t sb = smem_u32(dsm);
    uint32_t aOff = (uint32_t)((lane & 15) * PITCHB + (lane >> 4) * 16);
    uint32_t bOff = (uint32_t)(((lane >> 4) * 8 + (lane & 7)) * PITCHB + ((lane >> 3) & 1) * 16);

    float acc[2][8][4];
#pragma unroll
    for (int f = 0; f < 2; f++)
#pragma unroll
        for (int q = 0; q < 8; q++)
#pragma unroll
            for (int r = 0; r < 4; r++) acc[f][q][r] = 0.f;

    auto stage_copy = [&](int st, int c) {
        uint32_t stu = sb + st * STAGEB;
#pragma unroll
        for (int t = tid; t < 1024; t += 256) {
            int p = t >> 9, rem = t & 511, j = rem >> 8, r2 = rem & 255;
            int r = r2 >> 1, h = r2 & 1;
            const __nv_bfloat16* gA = p ? g_Alo : g_Ahi;
            const __nv_bfloat16* src = gA + (size_t)(m0 + r) * KPAD + c * 32 + j * 16 + h * 8;
            CP16(stu + (p * 2 + j) * A_SUB + r * PITCHB + h * 16, (const void*)src);
        }
#pragma unroll
        for (int t = tid; t < 1024; t += 256) {
            int p = t >> 9, rem = t & 511, j = rem >> 8, r2 = rem & 255;
            int n = r2 >> 1, h = r2 & 1;
            const __nv_bfloat16* gB = p ? g_Blo : g_Bhi;
            const __nv_bfloat16* src = gB + (size_t)n * KPAD + c * 32 + j * 16 + h * 8;
            CP16(stu + B_BASE + (p * 2 + j) * B_SUB + n * PITCHB + h * 16, (const void*)src);
        }
    };

    stage_copy(0, 0);
    CP_COMMIT();

    for (int c = 0; c < 34; c++) {
        CP_WAIT(0);
        __syncthreads();
        if (c + 1 < 34) { stage_copy((c + 1) & 1, c + 1); CP_COMMIT(); }

        uint32_t stu = sb + (c & 1) * STAGEB;
#pragma unroll
        for (int j = 0; j < 2; j++) {
            uint32_t ahi[2][4], alo[2][4], bfr[4][4];
#pragma unroll
            for (int f = 0; f < 2; f++) {
                uint32_t ra = (uint32_t)((wm * 32 + f * 16) * PITCHB) + aOff;
                LDMX4(ahi[f][0], ahi[f][1], ahi[f][2], ahi[f][3], stu + j * A_SUB + ra);
                LDMX4(alo[f][0], alo[f][1], alo[f][2], alo[f][3], stu + (2 + j) * A_SUB + ra);
            }
#pragma unroll
            for (int g = 0; g < 4; g++) {
                uint32_t rb = (uint32_t)((wn * 64 + g * 16) * PITCHB) + bOff;
                LDMX4(bfr[g][0], bfr[g][1], bfr[g][2], bfr[g][3], stu + B_BASE + j * B_SUB + rb);
            }
            // HH
#pragma unroll
            for (int g = 0; g < 4; g++)
#pragma unroll
                for (int f = 0; f < 2; f++) {
                    MMA16816(acc[f][2 * g],     ahi[f], bfr[g][0], bfr[g][1]);
                    MMA16816(acc[f][2 * g + 1], ahi[f], bfr[g][2], bfr[g][3]);
                }
            // LH
#pragma unroll
            for (int g = 0; g < 4; g++)
#pragma unroll
                for (int f = 0; f < 2; f++) {
                    MMA16816(acc[f][2 * g],     alo[f], bfr[g][0], bfr[g][1]);
                    MMA16816(acc[f][2 * g + 1], alo[f], bfr[g][2], bfr[g][3]);
                }
            // reload B-lo into same regs
#pragma unroll
            for (int g = 0; g < 4; g++) {
                uint32_t rb = (uint32_t)((wn * 64 + g * 16) * PITCHB) + bOff;
                LDMX4(bfr[g][0], bfr[g][1], bfr[g][2], bfr[g][3], stu + B_BASE + (2 + j) * B_SUB + rb);
            }
            // HL
#pragma unroll
            for (int g = 0; g < 4; g++)
#pragma unroll
                for (int f = 0; f < 2; f++) {
                    MMA16816(acc[f][2 * g],     ahi[f], bfr[g][0], bfr[g][1]);
                    MMA16816(acc[f][2 * g + 1], ahi[f], bfr[g][2], bfr[g][3]);
                }
        }
    }
    __syncthreads();

    // ---- epilogue: acc (+bias) -> T[128][129] ----
    float* T = (float*)dsm;
#pragma unroll
    for (int f = 0; f < 2; f++) {
        int r0 = wm * 32 + f * 16 + (lane >> 2);
#pragma unroll
        for (int q = 0; q < 8; q++) {
            int d = wn * 64 + q * 8 + (lane & 3) * 2;
            T[r0 * TPITCH + d]           = acc[f][q][0] + spb[d];
            T[r0 * TPITCH + d + 1]       = acc[f][q][1] + spb[d + 1];
            T[(r0 + 8) * TPITCH + d]     = acc[f][q][2] + spb[d];
            T[(r0 + 8) * TPITCH + d + 1] = acc[f][q][3] + spb[d + 1];
        }
    }
    __syncthreads();

    // ---- LayerNorm: 2 lanes per row (64 cols each) ----
    {
        int r = tid >> 1, q = tid & 1;
        float v[64];
        float s1 = 0.f, s2 = 0.f;
#pragma unroll
        for (int i = 0; i < 64; i++) {
            v[i] = T[r * TPITCH + q * 64 + i];
            s1 += v[i]; s2 += v[i] * v[i];
        }
        s1 += __shfl_xor_sync(0xffffffffu, s1, 1);
        s2 += __shfl_xor_sync(0xffffffffu, s2, 1);
        float mean = s1 * (1.f / 128.f);
        float var  = s2 * (1.f / 128.f) - mean * mean;
        float rs   = rsqrtf(var + 1e-5f);
#pragma unroll
        for (int i = 0; i < 64; i++) {
            int d = q * 64 + i;
            float y = (v[i] - mean) * rs * spg[d] + spe[d];
            T[r * TPITCH + d] = y > 0.f ? y : 0.2f * y;
        }
    }
    __syncthreads();

    // ---- coalesced transposed store ----
    int b = m0 >> 12, s0 = m0 & 4095;
    float* ob = out + (size_t)b * DOUT * Sn + s0;
    for (int i = tid; i < 128 * DOUT; i += 256) {
        int d = i >> 7, r = i & 127;
        ob[(size_t)d * Sn + r] = T[r * TPITCH + d];
    }
}

// ===========================================================================
extern "C" void kernel_launch(void* const* d_in, const int* in_sizes, int n_in,
                              void* d_out, int out_size)
{
    const float* xyz     = (const float*)d_in[0];
    const float* points  = (const float*)d_in[1];
    const float* new_xyz = (const float*)d_in[2];
    const int*   nn_idx  = (const int*)  d_in[3];
    const float* w0  = (const float*)d_in[4];
    const float* b0  = (const float*)d_in[5];
    const float* gm0 = (const float*)d_in[6];
    const float* be0 = (const float*)d_in[7];
    const float* w1  = (const float*)d_in[8];
    const float* b1  = (const float*)d_in[9];
    const float* gm1 = (const float*)d_in[10];
    const float* be1 = (const float*)d_in[11];
    const float* w2  = (const float*)d_in[12];
    const float* b2  = (const float*)d_in[13];
    const float* gm2 = (const float*)d_in[14];
    const float* be2 = (const float*)d_in[15];
    const float* wl  = (const float*)d_in[16];
    const float* bl  = (const float*)d_in[17];
    const float* gl  = (const float*)d_in[18];
    const float* bel = (const float*)d_in[19];
    float* out = (float*)d_out;

    static int inited = 0;
    static cudaStream_t sP = 0;
    static cudaEvent_t evStart, evP;
    if (!inited) {
        cudaFuncSetAttribute(k_gemm_mma, cudaFuncAttributeMaxDynamicSharedMemorySize,
                             GEMM_SMEM);
        cudaFuncSetAttribute(k_agg, cudaFuncAttributePreferredSharedMemoryCarveout,
                             cudaSharedmemCarveoutMaxShared);
        cudaStreamCreateWithFlags(&sP, cudaStreamNonBlocking);
        cudaEventCreateWithFlags(&evStart, cudaEventDisableTiming);
        cudaEventCreateWithFlags(&evP,     cudaEventDisableTiming);
        inited = 1;
    }

    // fork: prepB runs concurrently with fuse
    cudaEventRecord(evStart, 0);
    cudaStreamWaitEvent(sP, evStart, 0);
    k_prepB<<<(DOUT * KPAD + 255) / 256, 256, 0, sP>>>(wl);
    cudaEventRecord(evP, sP);

    dim3 gFuse(Nn / 32, Bn);
    k_fuse<<<gFuse, 256>>>(xyz, points);

    dim3 gAgg(Sn / PPB, Bn);
    k_agg<<<gAgg, 128>>>(nn_idx, new_xyz,
                         w0, b0, gm0, be0,
                         w1, b1, gm1, be1,
                         w2, b2, gm2, be2);

    cudaStreamWaitEvent(0, evP, 0);   // gemm needs prepB done
    k_gemm_mma<<<(Bn * Sn) / 128, 256, GEMM_SMEM>>>(bl, gl, bel, out);
}

// round 14
// speedup vs baseline: 1.2418x; 1.1582x over previous
#include <cuda_runtime.h>
#include <cuda_bf16.h>
#include <cuda_fp16.h>
#include <cstdint>

#define Bn   16
#define Nn   16384
#define Sn   4096
#define Kn   16
#define FC   68      // fused channels: 64 points + 3 xyz + 1 pad
#define CMID 16
#define DOUT 128
#define AGGD 1072    // 67*16
#define KPAD 1088    // 34 * 32

// Scratch (no allocations allowed -> __device__ globals; zero-initialized)
__device__ float g_fused[(size_t)Bn * Nn * FC];          // ~71 MB
__device__ __half g_Ahi[(size_t)Bn * Sn * KPAD];         // agg fp16 hi
__device__ __half g_Alo[(size_t)Bn * Sn * KPAD];         // agg fp16 lo (residual)
__device__ __half g_Bh[DOUT * KPAD];                     // wl^T fp16

__device__ __forceinline__ uint32_t smem_u32(const void* p) {
    uint32_t a;
    asm("{ .reg .u64 t; cvta.to.shared.u64 t, %1; cvt.u32.u64 %0, t; }" : "=r"(a) : "l"(p));
    return a;
}

#define LDMX4(r0, r1, r2, r3, addr)                                            \
    asm volatile("ldmatrix.sync.aligned.m8n8.x4.shared.b16 {%0,%1,%2,%3}, [%4];" \
                 : "=r"(r0), "=r"(r1), "=r"(r2), "=r"(r3) : "r"(addr))

#define MMA16816F16(acc, a, b0, b1)                                            \
    asm volatile("mma.sync.aligned.m16n8k16.row.col.f32.f16.f16.f32 "          \
                 "{%0,%1,%2,%3},{%4,%5,%6,%7},{%8,%9},{%0,%1,%2,%3};"          \
                 : "+f"((acc)[0]), "+f"((acc)[1]), "+f"((acc)[2]), "+f"((acc)[3]) \
                 : "r"((a)[0]), "r"((a)[1]), "r"((a)[2]), "r"((a)[3]),         \
                   "r"(b0), "r"(b1))

#define CP16(dst, src)                                                         \
    asm volatile("cp.async.cg.shared.global [%0], [%1], 16;" :: "r"(dst), "l"(src))
#define CP_COMMIT() asm volatile("cp.async.commit_group;" ::: "memory")
#define CP_WAIT(n)  asm volatile("cp.async.wait_group %0;" :: "n"(n) : "memory")

#define FMA_F32X2(d, a, b, c)                                                  \
    asm("fma.rn.f32x2 %0, %1, %2, %3;"                                         \
        : "=l"(d) : "l"(a), "l"(b), "l"(c))

// ===========================================================================
// Kernel 0: point-major fused feature array (vectorized)
// ===========================================================================
__global__ void k_fuse(const float* __restrict__ xyz, const float* __restrict__ points)
{
    __shared__ float t[32][69];
    int b = blockIdx.y, n0 = blockIdx.x * 32;
    for (int i = threadIdx.x; i < 544; i += 256) {
        int c = i >> 3, nq = i & 7;
        float4 v = make_float4(0.f, 0.f, 0.f, 0.f);
        if (c < 64)
            v = *(const float4*)&points[((size_t)b * 64 + c) * Nn + n0 + nq * 4];
        else if (c < 67)
            v = *(const float4*)&xyz[((size_t)b * 3 + (c - 64)) * Nn + n0 + nq * 4];
        t[nq * 4 + 0][c] = v.x;
        t[nq * 4 + 1][c] = v.y;
        t[nq * 4 + 2][c] = v.z;
        t[nq * 4 + 3][c] = v.w;
    }
    __syncthreads();
    float* dst = g_fused + ((size_t)b * Nn + n0) * FC;
    for (int i = threadIdx.x; i < 544; i += 256) {
        int r = i / 17, q = i - r * 17;
        float4 v = make_float4(t[r][q * 4], t[r][q * 4 + 1],
                               t[r][q * 4 + 2], t[r][q * 4 + 3]);
        *(float4*)&dst[r * FC + q * 4] = v;
    }
}

// ===========================================================================
// LayerNorm (+ leaky 0.2) helper
// ===========================================================================
template <int NCH>
__device__ __forceinline__ void ln_leaky(float* h, const float* gmm, const float* bt)
{
    const float inv = 1.f / (float)NCH;
    float m = 0.f;
#pragma unroll
    for (int j = 0; j < NCH; j++) m += h[j];
    m *= inv;
    float v = 0.f;
#pragma unroll
    for (int j = 0; j < NCH; j++) { float d = h[j] - m; v += d * d; }
    v *= inv;
    float r = rsqrtf(v + 1e-5f);
#pragma unroll
    for (int j = 0; j < NCH; j++) {
        float y = (h[j] - m) * r * gmm[j] + bt[j];
        h[j] = y > 0.f ? y : 0.2f * y;
    }
}

// ===========================================================================
// Kernel 1: 8 points per CTA (128 threads), flat 43.9 KB smem (5 CTAs/SM).
//   Aggregation via LDS.128 + 4 fma.rn.f32x2 chains; fp16 hi/lo emit.
// ===========================================================================
#define PPB 8
#define GW_PP  1092
#define WK_OFF 8732
#define WP_OFF (WK_OFF + 2048)
#define IDX_OFF (WP_OFF + 312)
#define NX_OFF (IDX_OFF + 128)
#define S_WORDS (NX_OFF + 24)

__global__ __launch_bounds__(128, 5)
void k_agg(const int* __restrict__ nn_idx, const float* __restrict__ new_xyz,
           const float* __restrict__ w0, const float* __restrict__ b0,
           const float* __restrict__ gm0, const float* __restrict__ be0,
           const float* __restrict__ w1, const float* __restrict__ b1,
           const float* __restrict__ gm1, const float* __restrict__ be1,
           const float* __restrict__ w2, const float* __restrict__ b2,
           const float* __restrict__ gm2, const float* __restrict__ be2)
{
    __shared__ float S[S_WORDS];
    float* wp = S + WP_OFF;
    int*   idxs = (int*)(S + IDX_OFF);
    float* nx = S + NX_OFF;

    int s0 = blockIdx.x * PPB, b = blockIdx.y;
    int tid = threadIdx.x;
    int pp = tid >> 4, kk = tid & 15;

    idxs[tid] = nn_idx[((size_t)b * Sn + s0) * Kn + tid];
    if (tid < 24) {
        int d = tid >> 3, q = tid & 7;
        nx[q * 3 + d] = new_xyz[(b * 3 + d) * Sn + s0 + q];
    }

    if (tid < 24) wp[tid] = w0[tid];
    if (tid < 8) {
        wp[24 + tid] = b0[tid];  wp[32 + tid] = gm0[tid]; wp[40 + tid] = be0[tid];
        wp[112 + tid] = b1[tid]; wp[120 + tid] = gm1[tid]; wp[128 + tid] = be1[tid];
    }
    if (tid < 64) wp[48 + tid] = w1[tid];
    wp[136 + tid] = w2[tid];
    if (tid < 16) {
        wp[264 + tid] = b2[tid]; wp[280 + tid] = gm2[tid]; wp[296 + tid] = be2[tid];
    }
    __syncthreads();

    // Gather: 8 points x 16 neighbors x 17 float4
#pragma unroll
    for (int it = 0; it < 17; it++) {
        int i = tid + it * 128;
        int pg = i / 272;
        int rem = i - pg * 272;
        int kg = rem / 17;
        int cg = rem - kg * 17;
        const float4* src = (const float4*)(g_fused + ((size_t)b * Nn + idxs[pg * 16 + kg]) * FC);
        ((float4*)(S + pg * GW_PP + kg * 68))[cg] = src[cg];
    }
    __syncthreads();

    // MLP: all 128 threads, one (point, neighbor) each
    {
        float* grow = S + pp * GW_PP + kk * 68;
        float x0 = grow[64] - nx[pp * 3 + 0];
        float x1 = grow[65] - nx[pp * 3 + 1];
        float x2 = grow[66] - nx[pp * 3 + 2];
        grow[64] = x0; grow[65] = x1; grow[66] = x2;

        float h[8];
#pragma unroll
        for (int j = 0; j < 8; j++)
            h[j] = x0 * wp[j] + x1 * wp[8 + j] + x2 * wp[16 + j] + wp[24 + j];
        ln_leaky<8>(h, wp + 32, wp + 40);

        float h2[8];
#pragma unroll
        for (int j = 0; j < 8; j++) {
            float a = wp[112 + j];
#pragma unroll
            for (int r = 0; r < 8; r++) a += h[r] * wp[48 + r * 8 + j];
            h2[j] = a;
        }
        ln_leaky<8>(h2, wp + 120, wp + 128);

        float h3[16];
#pragma unroll
        for (int j = 0; j < 16; j++) {
            float a = wp[264 + j];
#pragma unroll
            for (int r = 0; r < 8; r++) a += h2[r] * wp[136 + r * 16 + j];
            h3[j] = a;
        }
        ln_leaky<16>(h3, wp + 280, wp + 296);
#pragma unroll
        for (int j = 0; j < 16; j++) S[WK_OFF + pp * 256 + kk * 16 + j] = h3[j];
    }
    __syncthreads();

    // Aggregation
    {
        int t = kk;
        int p = t & 7;
        int cp0 = t >> 3;                 // 0 or 1

        unsigned long long ws0[Kn], ws1[Kn];
#pragma unroll
        for (int k = 0; k < Kn; k++) {
            float a0 = S[WK_OFF + pp * 256 + k * 16 + 2 * p];
            float a1 = S[WK_OFF + pp * 256 + k * 16 + 2 * p + 1];
            asm("mov.b64 %0, {%1, %1};" : "=l"(ws0[k]) : "f"(a0));
            asm("mov.b64 %0, {%1, %1};" : "=l"(ws1[k]) : "f"(a1));
        }

        uint32_t* hrow = (uint32_t*)(g_Ahi + ((size_t)b * Sn + s0 + pp) * KPAD);
        uint32_t* lrow = (uint32_t*)(g_Alo + ((size_t)b * Sn + s0 + pp) * KPAD);

        // emit c-pair: fp16 hi = rn(v), lo = rn(v - hi).  (m, m+1) packed per u32.
        auto emit = [&](int c, unsigned long long accA, unsigned long long accB) {
            float v00, v10, v01, v11;
            asm("mov.b64 {%0, %1}, %2;" : "=f"(v00), "=f"(v10) : "l"(accA));
            asm("mov.b64 {%0, %1}, %2;" : "=f"(v01), "=f"(v11) : "l"(accB));
            __half h00 = __float2half_rn(v00), h01 = __float2half_rn(v01);
            __half h10 = __float2half_rn(v10), h11 = __float2half_rn(v11);
            __half l00 = __float2half_rn(v00 - __half2float(h00));
            __half l01 = __float2half_rn(v01 - __half2float(h01));
            __half l10 = __float2half_rn(v10 - __half2float(h10));
            __half l11 = __float2half_rn(v11 - __half2float(h11));
            int ip0 = c * 8 + p, ip1 = (c + 1) * 8 + p;
            hrow[ip0] = (uint32_t)__half_as_ushort(h00) | ((uint32_t)__half_as_ushort(h01) << 16);
            hrow[ip1] = (uint32_t)__half_as_ushort(h10) | ((uint32_t)__half_as_ushort(h11) << 16);
            lrow[ip0] = (uint32_t)__half_as_ushort(l00) | ((uint32_t)__half_as_ushort(l01) << 16);
            lrow[ip1] = (uint32_t)__half_as_ushort(l10) | ((uint32_t)__half_as_ushort(l11) << 16);
        };

        const float* gbase = S + pp * GW_PP;
#pragma unroll 1
        for (int ii = 0; ii < 8; ii++) {
            int c = 4 * cp0 + 8 * ii;
            unsigned long long accA0 = 0ull, accB0 = 0ull;
            unsigned long long accA1 = 0ull, accB1 = 0ull;
#pragma unroll
            for (int k = 0; k < Kn; k++) {
                ulonglong2 fv = *(const ulonglong2*)(gbase + k * 68 + c);
                FMA_F32X2(accA0, fv.x, ws0[k], accA0);
                FMA_F32X2(accB0, fv.x, ws1[k], accB0);
                FMA_F32X2(accA1, fv.y, ws0[k], accA1);
                FMA_F32X2(accB1, fv.y, ws1[k], accB1);
            }
            emit(c,     accA0, accB0);
            emit(c + 2, accA1, accB1);
        }
        {   // tail: c = 64 + 2*cp0
            int c = 64 + 2 * cp0;
            unsigned long long accA = 0ull, accB = 0ull;
#pragma unroll
            for (int k = 0; k < Kn; k++) {
                unsigned long long fv2 = *(const unsigned long long*)(gbase + k * 68 + c);
                FMA_F32X2(accA, fv2, ws0[k], accA);
                FMA_F32X2(accB, fv2, ws1[k], accB);
            }
            emit(c, accA, accB);
        }
    }
}

// ===========================================================================
// Kernel 1.5: transpose wl [1072][128] -> [128][1088] fp16
// ===========================================================================
__global__ void k_prepB(const float* __restrict__ wl)
{
    int idx = blockIdx.x * 256 + threadIdx.x;
    if (idx >= DOUT * KPAD) return;
    int n = idx / KPAD, k = idx - n * KPAD;
    float v = (k < AGGD) ? wl[k * DOUT + n] : 0.f;
    g_Bh[idx] = __float2half_rn(v);
}

// ===========================================================================
// Kernel 2: pipelined mma.sync fp16 x2 GEMM [65536,1088]x[1088,128]
//   CTA tile 128x128, 8 warps (4m x 2n). Terms: Ah*B + Al*B (B single fp16).
// ===========================================================================
#define PITCHB   48
#define A_SUB    6144
#define B_SUB    6144
#define B_BASE   24576           // 4 A sub-blocks (hi/lo x 2 k16)
#define STAGEB   36864           // + 2 B sub-blocks
#define GEMM_SMEM (2 * STAGEB)
#define TPITCH   129

__global__ __launch_bounds__(256, 2)
void k_gemm_mma(const float* __restrict__ bl, const float* __restrict__ gl,
                const float* __restrict__ bel, float* __restrict__ out)
{
    extern __shared__ char dsm[];
    __shared__ float spb[DOUT], spg[DOUT], spe[DOUT];

    int tid = threadIdx.x;
    int wid = tid >> 5, lane = tid & 31;
    int wm = wid & 3, wn = wid >> 2;
    int m0 = blockIdx.x * 128;

    if (tid < DOUT) { spb[tid] = bl[tid]; spg[tid] = gl[tid]; spe[tid] = bel[tid]; }

    uint32_t sb = smem_u32(dsm);
    uint32_t aOff = (uint32_t)((lane & 15) * PITCHB + (lane >> 4) * 16);
    uint32_t bOff = (uint32_t)(((lane >> 4) * 8 + (lane & 7)) * PITCHB + ((lane >> 3) & 1) * 16);

    float acc[2][8][4];
#pragma unroll
    for (int f = 0; f < 2; f++)
#pragma unroll
        for (int q = 0; q < 8; q++)
#pragma unroll
            for (int r = 0; r < 4; r++) acc[f][q][r] = 0.f;

    auto stage_copy = [&](int st, int c) {
        uint32_t stu = sb + st * STAGEB;
#pragma unroll
        for (int t = tid; t < 1024; t += 256) {   // A: hi/lo, 2 k16-sub, 128 rows, 2 halves
            int p = t >> 9, rem = t & 511, j = rem >> 8, r2 = rem & 255;
            int r = r2 >> 1, h = r2 & 1;
            const __half* gA = p ? g_Alo : g_Ahi;
            const __half* src = gA + (size_t)(m0 + r) * KPAD + c * 32 + j * 16 + h * 8;
            CP16(stu + (p * 2 + j) * A_SUB + r * PITCHB + h * 16, (const void*)src);
        }
#pragma unroll
        for (int t = tid; t < 512; t += 256) {    // B: 2 k16-sub, 128 rows, 2 halves
            int j = t >> 8, r2 = t & 255;
            int n = r2 >> 1, h = r2 & 1;
            const __half* src = g_Bh + (size_t)n * KPAD + c * 32 + j * 16 + h * 8;
            CP16(stu + B_BASE + j * B_SUB + n * PITCHB + h * 16, (const void*)src);
        }
    };

    stage_copy(0, 0);
    CP_COMMIT();

    for (int c = 0; c < 34; c++) {
        CP_WAIT(0);
        __syncthreads();
        if (c + 1 < 34) { stage_copy((c + 1) & 1, c + 1); CP_COMMIT(); }

        uint32_t stu = sb + (c & 1) * STAGEB;
#pragma unroll
        for (int j = 0; j < 2; j++) {
            uint32_t ahi[2][4], alo[2][4], bfr[4][4];
#pragma unroll
            for (int f = 0; f < 2; f++) {
                uint32_t ra = (uint32_t)((wm * 32 + f * 16) * PITCHB) + aOff;
                LDMX4(ahi[f][0], ahi[f][1], ahi[f][2], ahi[f][3], stu + j * A_SUB + ra);
                LDMX4(alo[f][0], alo[f][1], alo[f][2], alo[f][3], stu + (2 + j) * A_SUB + ra);
            }
#pragma unroll
            for (int g = 0; g < 4; g++) {
                uint32_t rb = (uint32_t)((wn * 64 + g * 16) * PITCHB) + bOff;
                LDMX4(bfr[g][0], bfr[g][1], bfr[g][2], bfr[g][3], stu + B_BASE + j * B_SUB + rb);
            }
            // HH: Ah * B
#pragma unroll
            for (int g = 0; g < 4; g++)
#pragma unroll
                for (int f = 0; f < 2; f++) {
                    MMA16816F16(acc[f][2 * g],     ahi[f], bfr[g][0], bfr[g][1]);
                    MMA16816F16(acc[f][2 * g + 1], ahi[f], bfr[g][2], bfr[g][3]);
                }
            // LH: Al * B
#pragma unroll
            for (int g = 0; g < 4; g++)
#pragma unroll
                for (int f = 0; f < 2; f++) {
                    MMA16816F16(acc[f][2 * g],     alo[f], bfr[g][0], bfr[g][1]);
                    MMA16816F16(acc[f][2 * g + 1], alo[f], bfr[g][2], bfr[g][3]);
                }
        }
    }
    __syncthreads();

    // ---- epilogue: acc (+bias) -> T[128][129] ----
    float* T = (float*)dsm;
#pragma unroll
    for (int f = 0; f < 2; f++) {
        int r0 = wm * 32 + f * 16 + (lane >> 2);
#pragma unroll
        for (int q = 0; q < 8; q++) {
            int d = wn * 64 + q * 8 + (lane & 3) * 2;
            T[r0 * TPITCH + d]           = acc[f][q][0] + spb[d];
            T[r0 * TPITCH + d + 1]       = acc[f][q][1] + spb[d + 1];
            T[(r0 + 8) * TPITCH + d]     = acc[f][q][2] + spb[d];
            T[(r0 + 8) * TPITCH + d + 1] = acc[f][q][3] + spb[d + 1];
        }
    }
    __syncthreads();

    // ---- LayerNorm: 2 lanes per row (64 cols each) ----
    {
        int r = tid >> 1, q = tid & 1;
        float v[64];
        float s1 = 0.f, s2 = 0.f;
#pragma unroll
        for (int i = 0; i < 64; i++) {
            v[i] = T[r * TPITCH + q * 64 + i];
            s1 += v[i]; s2 += v[i] * v[i];
        }
        s1 += __shfl_xor_sync(0xffffffffu, s1, 1);
        s2 += __shfl_xor_sync(0xffffffffu, s2, 1);
        float mean = s1 * (1.f / 128.f);
        float var  = s2 * (1.f / 128.f) - mean * mean;
        float rs   = rsqrtf(var + 1e-5f);
#pragma unroll
        for (int i = 0; i < 64; i++) {
            int d = q * 64 + i;
            float y = (v[i] - mean) * rs * spg[d] + spe[d];
            T[r * TPITCH + d] = y > 0.f ? y : 0.2f * y;
        }
    }
    __syncthreads();

    // ---- coalesced transposed store ----
    int b = m0 >> 12, s0 = m0 & 4095;
    float* ob = out + (size_t)b * DOUT * Sn + s0;
    for (int i = tid; i < 128 * DOUT; i += 256) {
        int d = i >> 7, r = i & 127;
        ob[(size_t)d * Sn + r] = T[r * TPITCH + d];
    }
}

// ===========================================================================
extern "C" void kernel_launch(void* const* d_in, const int* in_sizes, int n_in,
                              void* d_out, int out_size)
{
    const float* xyz     = (const float*)d_in[0];
    const float* points  = (const float*)d_in[1];
    const float* new_xyz = (const float*)d_in[2];
    const int*   nn_idx  = (const int*)  d_in[3];
    const float* w0  = (const float*)d_in[4];
    const float* b0  = (const float*)d_in[5];
    const float* gm0 = (const float*)d_in[6];
    const float* be0 = (const float*)d_in[7];
    const float* w1  = (const float*)d_in[8];
    const float* b1  = (const float*)d_in[9];
    const float* gm1 = (const float*)d_in[10];
    const float* be1 = (const float*)d_in[11];
    const float* w2  = (const float*)d_in[12];
    const float* b2  = (const float*)d_in[13];
    const float* gm2 = (const float*)d_in[14];
    const float* be2 = (const float*)d_in[15];
    const float* wl  = (const float*)d_in[16];
    const float* bl  = (const float*)d_in[17];
    const float* gl  = (const float*)d_in[18];
    const float* bel = (const float*)d_in[19];
    float* out = (float*)d_out;

    static int inited = 0;
    static cudaStream_t sP = 0;
    static cudaEvent_t evStart, evP;
    if (!inited) {
        cudaFuncSetAttribute(k_gemm_mma, cudaFuncAttributeMaxDynamicSharedMemorySize,
                             GEMM_SMEM);
        cudaFuncSetAttribute(k_agg, cudaFuncAttributePreferredSharedMemoryCarveout,
                             cudaSharedmemCarveoutMaxShared);
        cudaStreamCreateWithFlags(&sP, cudaStreamNonBlocking);
        cudaEventCreateWithFlags(&evStart, cudaEventDisableTiming);
        cudaEventCreateWithFlags(&evP,     cudaEventDisableTiming);
        inited = 1;
    }

    // fork: prepB runs concurrently with fuse
    cudaEventRecord(evStart, 0);
    cudaStreamWaitEvent(sP, evStart, 0);
    k_prepB<<<(DOUT * KPAD + 255) / 256, 256, 0, sP>>>(wl);
    cudaEventRecord(evP, sP);

    dim3 gFuse(Nn / 32, Bn);
    k_fuse<<<gFuse, 256>>>(xyz, points);

    dim3 gAgg(Sn / PPB, Bn);
    k_agg<<<gAgg, 128>>>(nn_idx, new_xyz,
                         w0, b0, gm0, be0,
                         w1, b1, gm1, be1,
                         w2, b2, gm2, be2);

    cudaStreamWaitEvent(0, evP, 0);   // gemm needs prepB done
    k_gemm_mma<<<(Bn * Sn) / 128, 256, GEMM_SMEM>>>(bl, gl, bel, out);
}

// round 17
// speedup vs baseline: 1.5655x; 1.2607x over previous
#include <cuda_runtime.h>
#include <cuda_bf16.h>
#include <cuda_fp16.h>
#include <cstdint>

#define Bn   16
#define Nn   16384
#define Sn   4096
#define Kn   16
#define FC   68      // fused channels: 64 points + 3 xyz + 1 pad
#define CMID 16
#define DOUT 128
#define AGGD 1072    // 67*16
#define KPAD 1088    // 34 * 32

// Scratch (no allocations allowed -> __device__ globals; zero-initialized)
__device__ float g_fused[(size_t)Bn * Nn * FC];          // ~71 MB
__device__ __half g_Ah[(size_t)Bn * Sn * KPAD];          // agg fp16
__device__ __half g_Bh[DOUT * KPAD];                     // wl^T fp16

__device__ __forceinline__ uint32_t smem_u32(const void* p) {
    uint32_t a;
    asm("{ .reg .u64 t; cvta.to.shared.u64 t, %1; cvt.u32.u64 %0, t; }" : "=r"(a) : "l"(p));
    return a;
}

#define LDMX4(r0, r1, r2, r3, addr)                                            \
    asm volatile("ldmatrix.sync.aligned.m8n8.x4.shared.b16 {%0,%1,%2,%3}, [%4];" \
                 : "=r"(r0), "=r"(r1), "=r"(r2), "=r"(r3) : "r"(addr))

#define MMA16816F16(acc, a, b0, b1)                                            \
    asm volatile("mma.sync.aligned.m16n8k16.row.col.f32.f16.f16.f32 "          \
                 "{%0,%1,%2,%3},{%4,%5,%6,%7},{%8,%9},{%0,%1,%2,%3};"          \
                 : "+f"((acc)[0]), "+f"((acc)[1]), "+f"((acc)[2]), "+f"((acc)[3]) \
                 : "r"((a)[0]), "r"((a)[1]), "r"((a)[2]), "r"((a)[3]),         \
                   "r"(b0), "r"(b1))

#define CP16(dst, src)                                                         \
    asm volatile("cp.async.cg.shared.global [%0], [%1], 16;" :: "r"(dst), "l"(src))
#define CP_COMMIT() asm volatile("cp.async.commit_group;" ::: "memory")
#define CP_WAIT(n)  asm volatile("cp.async.wait_group %0;" :: "n"(n) : "memory")

#define FMA_F32X2(d, a, b, c)                                                  \
    asm("fma.rn.f32x2 %0, %1, %2, %3;"                                         \
        : "=l"(d) : "l"(a), "l"(b), "l"(c))

// ===========================================================================
// Kernel 0: point-major fused feature array (vectorized)
// ===========================================================================
__global__ void k_fuse(const float* __restrict__ xyz, const float* __restrict__ points)
{
    __shared__ float t[32][69];
    int b = blockIdx.y, n0 = blockIdx.x * 32;
    for (int i = threadIdx.x; i < 544; i += 256) {
        int c = i >> 3, nq = i & 7;
        float4 v = make_float4(0.f, 0.f, 0.f, 0.f);
        if (c < 64)
            v = *(const float4*)&points[((size_t)b * 64 + c) * Nn + n0 + nq * 4];
        else if (c < 67)
            v = *(const float4*)&xyz[((size_t)b * 3 + (c - 64)) * Nn + n0 + nq * 4];
        t[nq * 4 + 0][c] = v.x;
        t[nq * 4 + 1][c] = v.y;
        t[nq * 4 + 2][c] = v.z;
        t[nq * 4 + 3][c] = v.w;
    }
    __syncthreads();
    float* dst = g_fused + ((size_t)b * Nn + n0) * FC;
    for (int i = threadIdx.x; i < 544; i += 256) {
        int r = i / 17, q = i - r * 17;
        float4 v = make_float4(t[r][q * 4], t[r][q * 4 + 1],
                               t[r][q * 4 + 2], t[r][q * 4 + 3]);
        *(float4*)&dst[r * FC + q * 4] = v;
    }
}

// ===========================================================================
// LayerNorm (+ leaky 0.2) helper
// ===========================================================================
template <int NCH>
__device__ __forceinline__ void ln_leaky(float* h, const float* gmm, const float* bt)
{
    const float inv = 1.f / (float)NCH;
    float m = 0.f;
#pragma unroll
    for (int j = 0; j < NCH; j++) m += h[j];
    m *= inv;
    float v = 0.f;
#pragma unroll
    for (int j = 0; j < NCH; j++) { float d = h[j] - m; v += d * d; }
    v *= inv;
    float r = rsqrtf(v + 1e-5f);
#pragma unroll
    for (int j = 0; j < NCH; j++) {
        float y = (h[j] - m) * r * gmm[j] + bt[j];
        h[j] = y > 0.f ? y : 0.2f * y;
    }
}

// ===========================================================================
// Kernel 1: 8 points per CTA (128 threads), flat 43.9 KB smem (5 CTAs/SM).
//   Aggregation via LDS.128 + 4 fma.rn.f32x2 chains; single-fp16 emit.
// ===========================================================================
#define PPB 8
#define GW_PP  1092
#define WK_OFF 8732
#define WP_OFF (WK_OFF + 2048)
#define IDX_OFF (WP_OFF + 312)
#define NX_OFF (IDX_OFF + 128)
#define S_WORDS (NX_OFF + 24)

__global__ __launch_bounds__(128, 5)
void k_agg(const int* __restrict__ nn_idx, const float* __restrict__ new_xyz,
           const float* __restrict__ w0, const float* __restrict__ b0,
           const float* __restrict__ gm0, const float* __restrict__ be0,
           const float* __restrict__ w1, const float* __restrict__ b1,
           const float* __restrict__ gm1, const float* __restrict__ be1,
           const float* __restrict__ w2, const float* __restrict__ b2,
           const float* __restrict__ gm2, const float* __restrict__ be2)
{
    __shared__ float S[S_WORDS];
    float* wp = S + WP_OFF;
    int*   idxs = (int*)(S + IDX_OFF);
    float* nx = S + NX_OFF;

    int s0 = blockIdx.x * PPB, b = blockIdx.y;
    int tid = threadIdx.x;
    int pp = tid >> 4, kk = tid & 15;

    idxs[tid] = nn_idx[((size_t)b * Sn + s0) * Kn + tid];
    if (tid < 24) {
        int d = tid >> 3, q = tid & 7;
        nx[q * 3 + d] = new_xyz[(b * 3 + d) * Sn + s0 + q];
    }

    if (tid < 24) wp[tid] = w0[tid];
    if (tid < 8) {
        wp[24 + tid] = b0[tid];  wp[32 + tid] = gm0[tid]; wp[40 + tid] = be0[tid];
        wp[112 + tid] = b1[tid]; wp[120 + tid] = gm1[tid]; wp[128 + tid] = be1[tid];
    }
    if (tid < 64) wp[48 + tid] = w1[tid];
    wp[136 + tid] = w2[tid];
    if (tid < 16) {
        wp[264 + tid] = b2[tid]; wp[280 + tid] = gm2[tid]; wp[296 + tid] = be2[tid];
    }
    __syncthreads();

    // Gather: 8 points x 16 neighbors x 17 float4
#pragma unroll
    for (int it = 0; it < 17; it++) {
        int i = tid + it * 128;
        int pg = i / 272;
        int rem = i - pg * 272;
        int kg = rem / 17;
        int cg = rem - kg * 17;
        const float4* src = (const float4*)(g_fused + ((size_t)b * Nn + idxs[pg * 16 + kg]) * FC);
        ((float4*)(S + pg * GW_PP + kg * 68))[cg] = src[cg];
    }
    __syncthreads();

    // MLP: all 128 threads, one (point, neighbor) each
    {
        float* grow = S + pp * GW_PP + kk * 68;
        float x0 = grow[64] - nx[pp * 3 + 0];
        float x1 = grow[65] - nx[pp * 3 + 1];
        float x2 = grow[66] - nx[pp * 3 + 2];
        grow[64] = x0; grow[65] = x1; grow[66] = x2;

        float h[8];
#pragma unroll
        for (int j = 0; j < 8; j++)
            h[j] = x0 * wp[j] + x1 * wp[8 + j] + x2 * wp[16 + j] + wp[24 + j];
        ln_leaky<8>(h, wp + 32, wp + 40);

        float h2[8];
#pragma unroll
        for (int j = 0; j < 8; j++) {
            float a = wp[112 + j];
#pragma unroll
            for (int r = 0; r < 8; r++) a += h[r] * wp[48 + r * 8 + j];
            h2[j] = a;
        }
        ln_leaky<8>(h2, wp + 120, wp + 128);

        float h3[16];
#pragma unroll
        for (int j = 0; j < 16; j++) {
            float a = wp[264 + j];
#pragma unroll
            for (int r = 0; r < 8; r++) a += h2[r] * wp[136 + r * 16 + j];
            h3[j] = a;
        }
        ln_leaky<16>(h3, wp + 280, wp + 296);
#pragma unroll
        for (int j = 0; j < 16; j++) S[WK_OFF + pp * 256 + kk * 16 + j] = h3[j];
    }
    __syncthreads();

    // Aggregation
    {
        int t = kk;
        int p = t & 7;
        int cp0 = t >> 3;                 // 0 or 1

        unsigned long long ws0[Kn], ws1[Kn];
#pragma unroll
        for (int k = 0; k < Kn; k++) {
            float a0 = S[WK_OFF + pp * 256 + k * 16 + 2 * p];
            float a1 = S[WK_OFF + pp * 256 + k * 16 + 2 * p + 1];
            asm("mov.b64 %0, {%1, %1};" : "=l"(ws0[k]) : "f"(a0));
            asm("mov.b64 %0, {%1, %1};" : "=l"(ws1[k]) : "f"(a1));
        }

        uint32_t* hrow = (uint32_t*)(g_Ah + ((size_t)b * Sn + s0 + pp) * KPAD);

        // emit c-pair: single fp16 rn. (m, m+1) packed per u32.
        auto emit = [&](int c, unsigned long long accA, unsigned long long accB) {
            float v00, v10, v01, v11;
            asm("mov.b64 {%0, %1}, %2;" : "=f"(v00), "=f"(v10) : "l"(accA));
            asm("mov.b64 {%0, %1}, %2;" : "=f"(v01), "=f"(v11) : "l"(accB));
            uint32_t h0, h1;
            asm("cvt.rn.f16x2.f32 %0, %1, %2;" : "=r"(h0) : "f"(v01), "f"(v00));
            asm("cvt.rn.f16x2.f32 %0, %1, %2;" : "=r"(h1) : "f"(v11), "f"(v10));
            int ip0 = c * 8 + p, ip1 = (c + 1) * 8 + p;
            hrow[ip0] = h0; hrow[ip1] = h1;
        };

        const float* gbase = S + pp * GW_PP;
#pragma unroll 1
        for (int ii = 0; ii < 8; ii++) {
            int c = 4 * cp0 + 8 * ii;
            unsigned long long accA0 = 0ull, accB0 = 0ull;
            unsigned long long accA1 = 0ull, accB1 = 0ull;
#pragma unroll
            for (int k = 0; k < Kn; k++) {
                ulonglong2 fv = *(const ulonglong2*)(gbase + k * 68 + c);
                FMA_F32X2(accA0, fv.x, ws0[k], accA0);
                FMA_F32X2(accB0, fv.x, ws1[k], accB0);
                FMA_F32X2(accA1, fv.y, ws0[k], accA1);
                FMA_F32X2(accB1, fv.y, ws1[k], accB1);
            }
            emit(c,     accA0, accB0);
            emit(c + 2, accA1, accB1);
        }
        {   // tail: c = 64 + 2*cp0
            int c = 64 + 2 * cp0;
            unsigned long long accA = 0ull, accB = 0ull;
#pragma unroll
            for (int k = 0; k < Kn; k++) {
                unsigned long long fv2 = *(const unsigned long long*)(gbase + k * 68 + c);
                FMA_F32X2(accA, fv2, ws0[k], accA);
                FMA_F32X2(accB, fv2, ws1[k], accB);
            }
            emit(c, accA, accB);
        }
    }
}

// ===========================================================================
// Kernel 1.5: transpose wl [1072][128] -> [128][1088] fp16
// ===========================================================================
__global__ void k_prepB(const float* __restrict__ wl)
{
    int idx = blockIdx.x * 256 + threadIdx.x;
    if (idx >= DOUT * KPAD) return;
    int n = idx / KPAD, k = idx - n * KPAD;
    float v = (k < AGGD) ? wl[k * DOUT + n] : 0.f;
    g_Bh[idx] = __float2half_rn(v);
}

// ===========================================================================
// Kernel 2: pipelined mma.sync fp16 GEMM [65536,1088]x[1088,128]
//   CTA tile 128x128, 8 warps (4m x 2n). Single term: A * B.
//   NOTE: dynamic smem must cover BOTH 2*STAGEB (49152) and the epilogue
//   transpose buffer T[128][129] floats (66048) -> GEMM_SMEM = 66048.
// ===========================================================================
#define PITCHB   48
#define A_SUB    6144
#define B_SUB    6144
#define B_BASE   12288           // 2 A sub-blocks (2 k16)
#define STAGEB   24576           // + 2 B sub-blocks
#define TPITCH   129
#define GEMM_SMEM (128 * TPITCH * 4)   // 66048 >= 2*STAGEB

__global__ __launch_bounds__(256, 2)
void k_gemm_mma(const float* __restrict__ bl, const float* __restrict__ gl,
                const float* __restrict__ bel, float* __restrict__ out)
{
    extern __shared__ char dsm[];
    __shared__ float spb[DOUT], spg[DOUT], spe[DOUT];

    int tid = threadIdx.x;
    int wid = tid >> 5, lane = tid & 31;
    int wm = wid & 3, wn = wid >> 2;
    int m0 = blockIdx.x * 128;

    if (tid < DOUT) { spb[tid] = bl[tid]; spg[tid] = gl[tid]; spe[tid] = bel[tid]; }

    uint32_t sb = smem_u32(dsm);
    uint32_t aOff = (uint32_t)((lane & 15) * PITCHB + (lane >> 4) * 16);
    uint32_t bOff = (uint32_t)(((lane >> 4) * 8 + (lane & 7)) * PITCHB + ((lane >> 3) & 1) * 16);

    float acc[2][8][4];
#pragma unroll
    for (int f = 0; f < 2; f++)
#pragma unroll
        for (int q = 0; q < 8; q++)
#pragma unroll
            for (int r = 0; r < 4; r++) acc[f][q][r] = 0.f;

    auto stage_copy = [&](int st, int c) {
        uint32_t stu = sb + st * STAGEB;
#pragma unroll
        for (int t = tid; t < 512; t += 256) {    // A: 2 k16-sub, 128 rows, 2 halves
            int j = t >> 8, r2 = t & 255;
            int r = r2 >> 1, h = r2 & 1;
            const __half* src = g_Ah + (size_t)(m0 + r) * KPAD + c * 32 + j * 16 + h * 8;
            CP16(stu + j * A_SUB + r * PITCHB + h * 16, (const void*)src);
        }
#pragma unroll
        for (int t = tid; t < 512; t += 256) {    // B: 2 k16-sub, 128 rows, 2 halves
            int j = t >> 8, r2 = t & 255;
            int n = r2 >> 1, h = r2 & 1;
            const __half* src = g_Bh + (size_t)n * KPAD + c * 32 + j * 16 + h * 8;
            CP16(stu + B_BASE + j * B_SUB + n * PITCHB + h * 16, (const void*)src);
        }
    };

    stage_copy(0, 0);
    CP_COMMIT();

    for (int c = 0; c < 34; c++) {
        CP_WAIT(0);
        __syncthreads();
        if (c + 1 < 34) { stage_copy((c + 1) & 1, c + 1); CP_COMMIT(); }

        uint32_t stu = sb + (c & 1) * STAGEB;
#pragma unroll
        for (int j = 0; j < 2; j++) {
            uint32_t ahi[2][4], bfr[4][4];
#pragma unroll
            for (int f = 0; f < 2; f++) {
                uint32_t ra = (uint32_t)((wm * 32 + f * 16) * PITCHB) + aOff;
                LDMX4(ahi[f][0], ahi[f][1], ahi[f][2], ahi[f][3], stu + j * A_SUB + ra);
            }
#pragma unroll
            for (int g = 0; g < 4; g++) {
                uint32_t rb = (uint32_t)((wn * 64 + g * 16) * PITCHB) + bOff;
                LDMX4(bfr[g][0], bfr[g][1], bfr[g][2], bfr[g][3], stu + B_BASE + j * B_SUB + rb);
            }
#pragma unroll
            for (int g = 0; g < 4; g++)
#pragma unroll
                for (int f = 0; f < 2; f++) {
                    MMA16816F16(acc[f][2 * g],     ahi[f], bfr[g][0], bfr[g][1]);
                    MMA16816F16(acc[f][2 * g + 1], ahi[f], bfr[g][2], bfr[g][3]);
                }
        }
    }
    __syncthreads();

    // ---- epilogue: acc (+bias) -> T[128][129] ----
    float* T = (float*)dsm;
#pragma unroll
    for (int f = 0; f < 2; f++) {
        int r0 = wm * 32 + f * 16 + (lane >> 2);
#pragma unroll
        for (int q = 0; q < 8; q++) {
            int d = wn * 64 + q * 8 + (lane & 3) * 2;
            T[r0 * TPITCH + d]           = acc[f][q][0] + spb[d];
            T[r0 * TPITCH + d + 1]       = acc[f][q][1] + spb[d + 1];
            T[(r0 + 8) * TPITCH + d]     = acc[f][q][2] + spb[d];
            T[(r0 + 8) * TPITCH + d + 1] = acc[f][q][3] + spb[d + 1];
        }
    }
    __syncthreads();

    // ---- LayerNorm: 2 lanes per row (64 cols each) ----
    {
        int r = tid >> 1, q = tid & 1;
        float v[64];
        float s1 = 0.f, s2 = 0.f;
#pragma unroll
        for (int i = 0; i < 64; i++) {
            v[i] = T[r * TPITCH + q * 64 + i];
            s1 += v[i]; s2 += v[i] * v[i];
        }
        s1 += __shfl_xor_sync(0xffffffffu, s1, 1);
        s2 += __shfl_xor_sync(0xffffffffu, s2, 1);
        float mean = s1 * (1.f / 128.f);
        float var  = s2 * (1.f / 128.f) - mean * mean;
        float rs   = rsqrtf(var + 1e-5f);
#pragma unroll
        for (int i = 0; i < 64; i++) {
            int d = q * 64 + i;
            float y = (v[i] - mean) * rs * spg[d] + spe[d];
            T[r * TPITCH + d] = y > 0.f ? y : 0.2f * y;
        }
    }
    __syncthreads();

    // ---- coalesced transposed store ----
    int b = m0 >> 12, s0 = m0 & 4095;
    float* ob = out + (size_t)b * DOUT * Sn + s0;
    for (int i = tid; i < 128 * DOUT; i += 256) {
        int d = i >> 7, r = i & 127;
        ob[(size_t)d * Sn + r] = T[r * TPITCH + d];
    }
}

// ===========================================================================
extern "C" void kernel_launch(void* const* d_in, const int* in_sizes, int n_in,
                              void* d_out, int out_size)
{
    const float* xyz     = (const float*)d_in[0];
    const float* points  = (const float*)d_in[1];
    const float* new_xyz = (const float*)d_in[2];
    const int*   nn_idx  = (const int*)  d_in[3];
    const float* w0  = (const float*)d_in[4];
    const float* b0  = (const float*)d_in[5];
    const float* gm0 = (const float*)d_in[6];
    const float* be0 = (const float*)d_in[7];
    const float* w1  = (const float*)d_in[8];
    const float* b1  = (const float*)d_in[9];
    const float* gm1 = (const float*)d_in[10];
    const float* be1 = (const float*)d_in[11];
    const float* w2  = (const float*)d_in[12];
    const float* b2  = (const float*)d_in[13];
    const float* gm2 = (const float*)d_in[14];
    const float* be2 = (const float*)d_in[15];
    const float* wl  = (const float*)d_in[16];
    const float* bl  = (const float*)d_in[17];
    const float* gl  = (const float*)d_in[18];
    const float* bel = (const float*)d_in[19];
    float* out = (float*)d_out;

    static int inited = 0;
    static cudaStream_t sP = 0;
    static cudaEvent_t evStart, evP;
    if (!inited) {
        cudaFuncSetAttribute(k_gemm_mma, cudaFuncAttributeMaxDynamicSharedMemorySize,
                             GEMM_SMEM);
        cudaFuncSetAttribute(k_agg, cudaFuncAttributePreferredSharedMemoryCarveout,
                             cudaSharedmemCarveoutMaxShared);
        cudaStreamCreateWithFlags(&sP, cudaStreamNonBlocking);
        cudaEventCreateWithFlags(&evStart, cudaEventDisableTiming);
        cudaEventCreateWithFlags(&evP,     cudaEventDisableTiming);
        inited = 1;
    }

    // fork: prepB runs concurrently with fuse
    cudaEventRecord(evStart, 0);
    cudaStreamWaitEvent(sP, evStart, 0);
    k_prepB<<<(DOUT * KPAD + 255) / 256, 256, 0, sP>>>(wl);
    cudaEventRecord(evP, sP);

    dim3 gFuse(Nn / 32, Bn);
    k_fuse<<<gFuse, 256>>>(xyz, points);

    dim3 gAgg(Sn / PPB, Bn);
    k_agg<<<gAgg, 128>>>(nn_idx, new_xyz,
                         w0, b0, gm0, be0,
                         w1, b1, gm1, be1,
                         w2, b2, gm2, be2);

    cudaStreamWaitEvent(0, evP, 0);   // gemm needs prepB done
    k_gemm_mma<<<(Bn * Sn) / 128, 256, GEMM_SMEM>>>(bl, gl, bel, out);
}